// round 13
// baseline (speedup 1.0000x reference)
#include <cuda_runtime.h>
#include <math.h>
#include <stdint.h>

#define NN 100000
#define DD 128
#define CC 16
#define SS 16
#define KK 64
#define NIT 4
#define BMW 3125          // bitmap words for 100000 bits
#define HSZ 4096          // hash slots
#define NB  148           // persistent blocks (1 per SM -> all resident, barrier-safe)
#define KNOWN 0x80000000u

// ---------------- persistent device state (reset every launch) ----------------
__device__ unsigned int        g_nbr[NN];      // bits 0..15 class mask, bit31 = known
__device__ float               g_hx[CC * DD];
__device__ float               g_hxn[CC * DD];
__device__ int                 g_last[CC * KK];
__device__ int                 g_candCnt[CC];
__device__ unsigned int        g_barCount;
__device__ unsigned int        g_clist[(size_t)CC * NN];       // per-class node lists
__device__ unsigned long long  g_candKeys[(size_t)CC * NN];    // per-class key lists

// ---------------- helpers ----------------
__device__ __forceinline__ unsigned ford(float f) {
    unsigned u = __float_as_uint(f);
    return (u >> 31) ? ~u : (u | 0x80000000u);
}
__device__ __forceinline__ float iford(unsigned u) {
    unsigned v = (u >> 31) ? (u & 0x7FFFFFFFu) : ~u;
    return __uint_as_float(v);
}
__device__ __forceinline__ int hslot(unsigned v) {
    return (int)((v * 2654435761u) >> 20);
}
__device__ __forceinline__ void gridsync(unsigned target) {
    __syncthreads();
    if (threadIdx.x == 0) {
        __threadfence();
        atomicAdd(&g_barCount, 1u);
        while (*((volatile unsigned*)&g_barCount) < target) __nanosleep(32);
        __threadfence();
    }
    __syncthreads();
}

// ---------------- init (separate tiny launch) ----------------
__global__ void k_init() {
    int stride = gridDim.x * blockDim.x;
    int gt = blockIdx.x * blockDim.x + threadIdx.x;
    for (int v = gt; v < NN; v += stride) g_nbr[v] = 0u;
    if (gt < CC) g_candCnt[gt] = 0;
    if (gt == 0) g_barCount = 0u;
}

// ---------------- the persistent kernel ----------------
__global__ void __launch_bounds__(1024) k_main(
        const float* __restrict__ es, const float* __restrict__ W,
        const int* __restrict__ seeds,
        const int* __restrict__ src, const int* __restrict__ dst, int e,
        float* __restrict__ outP, float* __restrict__ outE,
        float* __restrict__ outHxes) {
    __shared__ __align__(16) unsigned char s_raw[45312];
    const int tid = threadIdx.x;
    const int bid = blockIdx.x;
    const int lane = tid & 31;
    unsigned bargen = 0;

    for (int t = 0; t < NIT; t++) {
        const int per = (t == 0) ? SS : KK;
        const int nm = CC * per;

        // ================= PHASE A: memory (blocks 0..15) | edges (16..147) =========
        if (bid >= CC) {
            unsigned* bm    = reinterpret_cast<unsigned*>(s_raw);
            unsigned* hkey  = reinterpret_cast<unsigned*>(s_raw + 12512);
            unsigned* hmask = reinterpret_cast<unsigned*>(s_raw + 12512 + 16384);
            const int b2 = bid - CC;

            for (int i = tid; i < BMW; i += 1024) bm[i] = 0u;
            for (int i = tid; i < HSZ; i += 1024) { hkey[i] = 0u; hmask[i] = 0u; }
            __syncthreads();
            if (tid < nm) {
                int m = tid;
                unsigned u = (unsigned)((t == 0) ? seeds[m] : __ldcg(&g_last[m]));
                unsigned bit = 1u << (m / per);
                atomicOr(&bm[u >> 5], 1u << (u & 31));
                int s = hslot(u);
                for (;;) {
                    unsigned k = atomicCAS(&hkey[s], 0u, u + 1u);
                    if (k == 0u || k == u + 1u) { atomicOr(&hmask[s], bit); break; }
                    s = (s + 1) & (HSZ - 1);
                }
                if (b2 == 0) atomicOr(&g_nbr[u], KNOWN);
            }
            __syncthreads();

            const int e4 = e >> 2;
            const int4* s4 = reinterpret_cast<const int4*>(src);
            const int stride = (NB - CC) * 1024;
#pragma unroll 4
            for (int i = b2 * 1024 + tid; i < e4; i += stride) {
                int4 s = s4[i];
#pragma unroll
                for (int q = 0; q < 4; q++) {
                    unsigned u = (unsigned)((q == 0) ? s.x : (q == 1) ? s.y : (q == 2) ? s.z : s.w);
                    if ((bm[u >> 5] >> (u & 31)) & 1u) {
                        int sl = hslot(u);
                        unsigned m;
                        for (;;) {
                            unsigned k = hkey[sl];
                            if (k == u + 1u) { m = hmask[sl]; break; }
                            sl = (sl + 1) & (HSZ - 1);
                        }
                        atomicOr(&g_nbr[dst[4 * i + q]], m);
                    }
                }
            }
            int tail = e & 3, tb = e - tail;
            if (b2 == 0 && tid < tail) {
                unsigned u = (unsigned)src[tb + tid];
                if ((bm[u >> 5] >> (u & 31)) & 1u) {
                    int sl = hslot(u);
                    unsigned m;
                    for (;;) {
                        unsigned k = hkey[sl];
                        if (k == u + 1u) { m = hmask[sl]; break; }
                        sl = (sl + 1) & (HSZ - 1);
                    }
                    atomicOr(&g_nbr[dst[tb + tid]], m);
                }
            }
        } else {
            // ---------- memory role ----------
            float* s_inp  = reinterpret_cast<float*>(s_raw);              // 32768
            float* s_part = reinterpret_cast<float*>(s_raw + 32768);      // 4096
            float* s_q    = reinterpret_cast<float*>(s_raw + 36864);      // 512
            float* s_a    = reinterpret_cast<float*>(s_raw + 37376);      // 256
            float* s_pre  = reinterpret_cast<float*>(s_raw + 37632);      // 512
            float* s_red  = reinterpret_cast<float*>(s_raw + 38144);      // 64

            const int c = bid;
            const int g = tid >> 7;
            const int d = tid & 127;
            const int kk = per;

            for (int j = g; j < kk; j += 8) {
                int node = (t == 0) ? seeds[c * kk + j] : __ldcg(&g_last[c * KK + j]);
                s_inp[j * DD + d] = es[(size_t)node * DD + d];
            }
            if (t == 0) {
                float part = 0.0f;
                for (int j = g; j < kk; j += 8) part += s_inp[j * DD + d];
                s_part[g * DD + d] = part;
                __syncthreads();
                if (g == 0) {
                    float s = 0.0f;
#pragma unroll
                    for (int i = 0; i < 8; i++) s += s_part[i * DD + d];
                    s_q[d] = s / (float)kk;
                }
            } else {
                if (g == 0) s_q[d] = g_hx[c * DD + d];
            }
            __syncthreads();

            int jw = tid >> 5;
            for (int j = jw; j < kk; j += 32) {
                float p = 0.0f;
#pragma unroll
                for (int q = 0; q < 4; q++) {
                    int dd = lane + 32 * q;
                    p += s_inp[j * DD + dd] * s_q[dd];
                }
#pragma unroll
                for (int o = 16; o; o >>= 1) p += __shfl_xor_sync(0xffffffffu, p, o);
                if (lane == 0) s_a[j] = p / sqrtf(128.0f);
            }
            __syncthreads();
            if (tid < 32) {
                float a0 = (tid < kk) ? s_a[tid] : -1e30f;
                float a1 = (tid + 32 < kk) ? s_a[tid + 32] : -1e30f;
                float m = fmaxf(a0, a1);
#pragma unroll
                for (int o = 16; o; o >>= 1) m = fmaxf(m, __shfl_xor_sync(0xffffffffu, m, o));
                float e0 = (tid < kk) ? expf(a0 - m) : 0.0f;
                float e1 = (tid + 32 < kk) ? expf(a1 - m) : 0.0f;
                float s = e0 + e1;
#pragma unroll
                for (int o = 16; o; o >>= 1) s += __shfl_xor_sync(0xffffffffu, s, o);
                if (tid < kk) s_a[tid] = e0 / s;
                if (tid + 32 < kk) s_a[tid + 32] = e1 / s;
            }
            __syncthreads();
            {
                float part = 0.0f;
                for (int j = g; j < kk; j += 8) part += s_a[j] * s_inp[j * DD + d];
                s_part[g * DD + d] = part;
            }
            __syncthreads();
            if (g == 0) {
                float ctx = 0.0f;
#pragma unroll
                for (int i = 0; i < 8; i++) ctx += s_part[i * DD + d];
                s_pre[d] = ctx + ((t > 0) ? s_q[d] : 0.0f);
            }
            __syncthreads();
            {
                float part = 0.0f;
                const int i0 = g * 16;
#pragma unroll 4
                for (int i = i0; i < i0 + 16; i++) part += s_pre[i] * W[i * DD + d];
                s_part[g * DD + d] = part;
            }
            __syncthreads();
            float h = 0.0f;
            if (g == 0) {
                float acc = 0.0f;
#pragma unroll
                for (int i = 0; i < 8; i++) acc += s_part[i * DD + d];
                h = tanhf(acc);
                g_hx[c * DD + d] = h;
                outHxes[(t * CC + c) * DD + d] = h;
                float ss = h * h;
#pragma unroll
                for (int o = 16; o; o >>= 1) ss += __shfl_xor_sync(0xffffffffu, ss, o);
                if (lane == 0) s_red[tid >> 5] = ss;
            }
            __syncthreads();
            if (g == 0) {
                float ns = s_red[0] + s_red[1] + s_red[2] + s_red[3];
                g_hxn[c * DD + d] = h / (sqrtf(ns) + 1e-8f);
            }
        }

        bargen += NB; gridsync(bargen);

        // ======== PHASE B1: per-class compaction, rank-based (no per-entry atomics) ==
        {
            int (*s_wcnt)[17] = reinterpret_cast<int(*)[17]>(s_raw);            // 32x17
            int (*s_woff)[17] = reinterpret_cast<int(*)[17]>(s_raw + 2304);     // 32x17
            int* s_base = reinterpret_cast<int*>(s_raw + 4608);                 // 16

            const int w = tid >> 5;
            int v = bid * 1024 + tid;
            unsigned m = 0u;
            if (v < NN) {
                m = __ldcg(&g_nbr[v]);
                m = (m & KNOWN) ? 0u : (m & 0xFFFFu);
            }
            // stage 1: per-warp per-class counts
#pragma unroll
            for (int c2 = 0; c2 < CC; c2++) {
                unsigned b = __ballot_sync(0xffffffffu, (m >> c2) & 1u);
                if (lane == 0) s_wcnt[w][c2] = __popc(b);
            }
            __syncthreads();
            // stage 2: per-class scan over 32 warps (warp c2 handles class c2)
            if (tid < CC * 32) {
                int c2 = tid >> 5;
                int lw = lane;
                int val = s_wcnt[lw][c2];
                int x = val;
#pragma unroll
                for (int o = 1; o < 32; o <<= 1) {
                    int y = __shfl_up_sync(0xffffffffu, x, o);
                    if (lw >= o) x += y;
                }
                s_woff[lw][c2] = x - val;
                if (lw == 31) {
                    int total = x;
                    s_base[c2] = total ? atomicAdd(&g_candCnt[c2], total) : 0;
                }
            }
            __syncthreads();
            // stage 3: rank within warp, write
#pragma unroll
            for (int c2 = 0; c2 < CC; c2++) {
                unsigned b = __ballot_sync(0xffffffffu, (m >> c2) & 1u);
                if ((m >> c2) & 1u) {
                    int rank = __popc(b & ((1u << lane) - 1u));
                    int pos = s_base[c2] + s_woff[w][c2] + rank;
                    g_clist[(size_t)c2 * NN + pos] = (unsigned)v;
                }
            }
        }

        bargen += NB; gridsync(bargen);

        // ======== PHASE B2: score per-class segments, keys at own index (no atomics) =
        {
            float* sh = reinterpret_cast<float*>(s_raw);
            int* s_cnt = reinterpret_cast<int*>(s_raw + 8192);
            for (int i = tid; i < CC * DD; i += 1024) sh[i] = __ldcg(&g_hxn[i]);
            if (tid < CC) s_cnt[tid] = atomicAdd(&g_candCnt[tid], 0);
            __syncthreads();
            const float4* sh4 = reinterpret_cast<const float4*>(sh);
            const float4* es4 = reinterpret_cast<const float4*>(es);
            const int gw = (bid * 1024 + tid) >> 5;
            const int nwarp = NB * 32;
            for (int c2 = 0; c2 < CC; c2++) {
                const int cntc = s_cnt[c2];
                const unsigned* lst = g_clist + (size_t)c2 * NN;
                unsigned long long* keyseg = g_candKeys + (size_t)c2 * NN;
                const float4 h = sh4[c2 * 32 + lane];
                for (int base = gw * 4; base < cntc; base += nwarp * 4) {
                    int n = cntc - base; if (n > 4) n = 4;
                    float ssum[4], dsum[4];
                    unsigned vv[4];
#pragma unroll
                    for (int k = 0; k < 4; k++) {
                        ssum[k] = 0.0f; dsum[k] = 0.0f; vv[k] = 0u;
                        if (k < n) {
                            unsigned v = __ldcg(&lst[base + k]);
                            vv[k] = v;
                            const float4 r = es4[(size_t)v * 32 + lane];
                            ssum[k] = r.x * r.x + r.y * r.y + r.z * r.z + r.w * r.w;
                            dsum[k] = r.x * h.x + r.y * h.y + r.z * h.z + r.w * h.w;
                        }
                    }
#pragma unroll
                    for (int k = 0; k < 4; k++) {
#pragma unroll
                        for (int o = 16; o; o >>= 1) {
                            ssum[k] += __shfl_xor_sync(0xffffffffu, ssum[k], o);
                            dsum[k] += __shfl_xor_sync(0xffffffffu, dsum[k], o);
                        }
                    }
                    float sc0 = dsum[0] * (1.0f / (sqrtf(ssum[0]) + 1e-8f));
                    float sc1 = dsum[1] * (1.0f / (sqrtf(ssum[1]) + 1e-8f));
                    float sc2 = dsum[2] * (1.0f / (sqrtf(ssum[2]) + 1e-8f));
                    float sc3 = dsum[3] * (1.0f / (sqrtf(ssum[3]) + 1e-8f));
                    if (lane < n) {
                        float score = (lane == 0) ? sc0 : (lane == 1) ? sc1 : (lane == 2) ? sc2 : sc3;
                        unsigned v = (lane == 0) ? vv[0] : (lane == 1) ? vv[1] : (lane == 2) ? vv[2] : vv[3];
                        unsigned long long key =
                            ((unsigned long long)ford(score) << 32) |
                            (unsigned long long)(0xFFFFFFFFu - v);
                        keyseg[base + lane] = key;
                    }
                }
            }
        }

        bargen += NB; gridsync(bargen);

        // ================= PHASE C: topk (blocks 0..15), per-class segments ==========
        if (bid < CC) {
            unsigned* hist = reinterpret_cast<unsigned*>(s_raw);
            unsigned long long* sbuf = reinterpret_cast<unsigned long long*>(s_raw + 16384);
            unsigned* s_wsum = reinterpret_cast<unsigned*>(s_raw + 20480);
            int* s_sc = reinterpret_cast<int*>(s_raw + 20608);

            const int c = bid;
            const int wid = tid >> 5;
            const unsigned long long* keys = g_candKeys + (size_t)c * NN;
            int cnt = atomicAdd(&g_candCnt[c], 0);
            __syncthreads();
            if (tid == 0) atomicExch(&g_candCnt[c], 0);   // reset for next iter's B1
            int r = cnt < KK ? cnt : KK;

            unsigned long long prefix = 0ULL;
            int sf = 64;
            if (cnt > 512) {
                int rr = r;
                for (int shift = 52; shift >= 4; shift -= 12) {
                    for (int j = tid; j < 4096; j += 1024) hist[j] = 0u;
                    __syncthreads();
                    for (int i = tid; i < cnt; i += 1024) {
                        unsigned long long key = __ldcg(&keys[i]);
                        if (sf >= 64 || (key >> sf) == prefix)
                            atomicAdd(&hist[(unsigned)((key >> shift) & 0xFFFULL)], 1u);
                    }
                    __syncthreads();
                    int b4 = tid * 4;
                    unsigned lsum = hist[b4] + hist[b4 + 1] + hist[b4 + 2] + hist[b4 + 3];
                    unsigned x = lsum;
#pragma unroll
                    for (int off = 1; off < 32; off <<= 1) {
                        unsigned y = __shfl_down_sync(0xffffffffu, x, off);
                        if (lane + off < 32) x += y;
                    }
                    if (lane == 0) s_wsum[wid] = x;
                    __syncthreads();
                    if (wid == 0) {
                        unsigned w2 = s_wsum[lane];
                        unsigned own = w2;
#pragma unroll
                        for (int off = 1; off < 32; off <<= 1) {
                            unsigned y = __shfl_down_sync(0xffffffffu, w2, off);
                            if (lane + off < 32) w2 += y;
                        }
                        s_wsum[lane] = w2 - own;
                    }
                    __syncthreads();
                    unsigned incl = x + s_wsum[wid];
                    unsigned above = incl - lsum;
                    if (above < (unsigned)rr && incl >= (unsigned)rr) {
                        unsigned cum = above;
                        for (int b = b4 + 3; b >= b4; --b) {
                            unsigned h2 = hist[b];
                            if (cum + h2 >= (unsigned)rr) {
                                s_sc[0] = b;
                                s_sc[1] = (int)cum;
                                int aboveTot = (r - rr) + (int)cum;
                                s_sc[2] = (aboveTot + (int)h2 <= 256) ? 1 : 0;
                                break;
                            }
                            cum += h2;
                        }
                    }
                    __syncthreads();
                    prefix = (prefix << 12) | (unsigned long long)s_sc[0];
                    rr -= s_sc[1];
                    sf = shift;
                    int stop = s_sc[2];
                    __syncthreads();
                    if (stop) break;
                }
            }
            if (tid == 0) s_sc[3] = 0;
            __syncthreads();
            for (int i = tid; i < cnt; i += 1024) {
                unsigned long long key = __ldcg(&keys[i]);
                bool take = (sf >= 64) || ((key >> sf) >= prefix);
                if (take) {
                    int p = atomicAdd(&s_sc[3], 1);
                    if (p < 512) sbuf[p] = key;
                }
            }
            __syncthreads();
            int sc = s_sc[3] < 512 ? s_sc[3] : 512;
            int n = (sc <= 256) ? 256 : 512;
            if (tid < n && tid >= sc) sbuf[tid] = 0ULL;
            __syncthreads();
            for (int kk2 = 2; kk2 <= n; kk2 <<= 1) {
                for (int j = kk2 >> 1; j > 0; j >>= 1) {
                    if (tid < n) {
                        int ixj = tid ^ j;
                        if (ixj > tid) {
                            unsigned long long a = sbuf[tid], b = sbuf[ixj];
                            bool desc = ((tid & kk2) == 0);
                            if (desc ? (a < b) : (a > b)) { sbuf[tid] = b; sbuf[ixj] = a; }
                        }
                    }
                    __syncthreads();
                }
            }
            const int base = (t * CC + c) * KK;
            if (tid < KK && tid < r) {
                unsigned long long key = sbuf[tid];
                int v = (int)(0xFFFFFFFFu - (unsigned)(key & 0xFFFFFFFFull));
                outP[base + tid] = iford((unsigned)(key >> 32));
                outE[base + tid] = (float)v;
                g_last[c * KK + tid] = v;
            }
            if (tid == 0 && r < KK) {
                int fill = r;
                for (int v = 0; v < NN && fill < KK; v++) {
                    unsigned m = __ldcg(&g_nbr[v]);
                    bool valid = (((m >> c) & 1u) != 0u) && !(m & KNOWN);
                    if (!valid) {
                        outP[base + fill] = -1e9f;
                        outE[base + fill] = (float)v;
                        g_last[c * KK + fill] = v;
                        fill++;
                    }
                }
            }
        }

        if (t < NIT - 1) { bargen += NB; gridsync(bargen); }
    }
}

// ---------------- launch ----------------
extern "C" void kernel_launch(void* const* d_in, const int* in_sizes, int n_in,
                              void* d_out, int out_size) {
    const float* es    = (const float*)d_in[0];
    const int*   edges = (const int*)d_in[1];
    const int*   seeds = (const int*)d_in[2];
    const float* W     = (const float*)d_in[3];
    (void)n_in; (void)out_size;

    int e = in_sizes[1] / 2;
    const int* src = edges;
    const int* dst = edges + e;

    float* out  = (float*)d_out;
    float* outP = out;
    float* outE = out + NIT * CC * KK;
    float* outH = out + 2 * NIT * CC * KK;

    k_init<<<128, 256>>>();
    k_main<<<NB, 1024>>>(es, W, seeds, src, dst, e, outP, outE, outH);
}

// round 14
// speedup vs baseline: 1.2293x; 1.2293x over previous
#include <cuda_runtime.h>
#include <math.h>
#include <stdint.h>

#define NN 100000
#define DD 128
#define CC 16
#define SS 16
#define KK 64
#define NIT 4
#define BMW 3125          // bitmap words for 100000 bits
#define HSZ 4096          // hash slots
#define NB  148           // persistent blocks (1 per SM -> all resident, barrier-safe)
#define KNOWN 0x80000000u

// ---------------- persistent device state (reset every launch) ----------------
__device__ unsigned int        g_nbr[NN];      // bits 0..15 class mask, bit31 = known
__device__ float               g_hx[CC * DD];
__device__ float               g_hxn[CC * DD];
__device__ int                 g_last[CC * KK];
__device__ int                 g_candCnt[CC];
__device__ unsigned int        g_barCount;
__device__ unsigned int        g_clist[(size_t)CC * NN];       // per-class node lists
__device__ unsigned long long  g_candKeys[(size_t)CC * NN];    // per-class key lists

// ---------------- helpers ----------------
__device__ __forceinline__ unsigned ford(float f) {
    unsigned u = __float_as_uint(f);
    return (u >> 31) ? ~u : (u | 0x80000000u);
}
__device__ __forceinline__ float iford(unsigned u) {
    unsigned v = (u >> 31) ? (u & 0x7FFFFFFFu) : ~u;
    return __uint_as_float(v);
}
__device__ __forceinline__ int hslot(unsigned v) {
    return (int)((v * 2654435761u) >> 20);
}
__device__ __forceinline__ void gridsync(unsigned target) {
    __syncthreads();
    if (threadIdx.x == 0) {
        __threadfence();
        atomicAdd(&g_barCount, 1u);
        while (*((volatile unsigned*)&g_barCount) < target) __nanosleep(32);
        __threadfence();
    }
    __syncthreads();
}

// ---------------- init (separate tiny launch) ----------------
__global__ void k_init() {
    int stride = gridDim.x * blockDim.x;
    int gt = blockIdx.x * blockDim.x + threadIdx.x;
    for (int v = gt; v < NN; v += stride) g_nbr[v] = 0u;
    if (gt < CC) g_candCnt[gt] = 0;
    if (gt == 0) g_barCount = 0u;
}

// ---------------- the persistent kernel ----------------
__global__ void __launch_bounds__(1024) k_main(
        const float* __restrict__ es, const float* __restrict__ W,
        const int* __restrict__ seeds,
        const int* __restrict__ src, const int* __restrict__ dst, int e,
        float* __restrict__ outP, float* __restrict__ outE,
        float* __restrict__ outHxes) {
    __shared__ __align__(16) unsigned char s_raw[45312];
    const int tid = threadIdx.x;
    const int bid = blockIdx.x;
    const int lane = tid & 31;
    unsigned bargen = 0;

    for (int t = 0; t < NIT; t++) {
        const int per = (t == 0) ? SS : KK;
        const int nm = CC * per;

        // ================= PHASE A: memory (blocks 0..15) | edges (16..147) =========
        if (bid >= CC) {
            unsigned* bm    = reinterpret_cast<unsigned*>(s_raw);
            unsigned* hkey  = reinterpret_cast<unsigned*>(s_raw + 12512);
            unsigned* hmask = reinterpret_cast<unsigned*>(s_raw + 12512 + 16384);
            const int b2 = bid - CC;

            for (int i = tid; i < BMW; i += 1024) bm[i] = 0u;
            for (int i = tid; i < HSZ; i += 1024) { hkey[i] = 0u; hmask[i] = 0u; }
            __syncthreads();
            if (tid < nm) {
                int m = tid;
                unsigned u = (unsigned)((t == 0) ? seeds[m] : __ldcg(&g_last[m]));
                unsigned bit = 1u << (m / per);
                atomicOr(&bm[u >> 5], 1u << (u & 31));
                int s = hslot(u);
                for (;;) {
                    unsigned k = atomicCAS(&hkey[s], 0u, u + 1u);
                    if (k == 0u || k == u + 1u) { atomicOr(&hmask[s], bit); break; }
                    s = (s + 1) & (HSZ - 1);
                }
                if (b2 == 0) atomicOr(&g_nbr[u], KNOWN);
            }
            __syncthreads();

            const int e4 = e >> 2;
            const int4* s4 = reinterpret_cast<const int4*>(src);
            const int stride = (NB - CC) * 1024;
#pragma unroll 4
            for (int i = b2 * 1024 + tid; i < e4; i += stride) {
                int4 s = s4[i];
#pragma unroll
                for (int q = 0; q < 4; q++) {
                    unsigned u = (unsigned)((q == 0) ? s.x : (q == 1) ? s.y : (q == 2) ? s.z : s.w);
                    if ((bm[u >> 5] >> (u & 31)) & 1u) {
                        int sl = hslot(u);
                        unsigned m;
                        for (;;) {
                            unsigned k = hkey[sl];
                            if (k == u + 1u) { m = hmask[sl]; break; }
                            sl = (sl + 1) & (HSZ - 1);
                        }
                        atomicOr(&g_nbr[dst[4 * i + q]], m);
                    }
                }
            }
            int tail = e & 3, tb = e - tail;
            if (b2 == 0 && tid < tail) {
                unsigned u = (unsigned)src[tb + tid];
                if ((bm[u >> 5] >> (u & 31)) & 1u) {
                    int sl = hslot(u);
                    unsigned m;
                    for (;;) {
                        unsigned k = hkey[sl];
                        if (k == u + 1u) { m = hmask[sl]; break; }
                        sl = (sl + 1) & (HSZ - 1);
                    }
                    atomicOr(&g_nbr[dst[tb + tid]], m);
                }
            }
        } else {
            // ---------- memory role ----------
            float* s_inp  = reinterpret_cast<float*>(s_raw);              // 32768
            float* s_part = reinterpret_cast<float*>(s_raw + 32768);      // 4096
            float* s_q    = reinterpret_cast<float*>(s_raw + 36864);      // 512
            float* s_a    = reinterpret_cast<float*>(s_raw + 37376);      // 256
            float* s_pre  = reinterpret_cast<float*>(s_raw + 37632);      // 512
            float* s_red  = reinterpret_cast<float*>(s_raw + 38144);      // 64

            const int c = bid;
            const int g = tid >> 7;
            const int d = tid & 127;
            const int kk = per;

            for (int j = g; j < kk; j += 8) {
                int node = (t == 0) ? seeds[c * kk + j] : __ldcg(&g_last[c * KK + j]);
                s_inp[j * DD + d] = es[(size_t)node * DD + d];
            }
            if (t == 0) {
                float part = 0.0f;
                for (int j = g; j < kk; j += 8) part += s_inp[j * DD + d];
                s_part[g * DD + d] = part;
                __syncthreads();
                if (g == 0) {
                    float s = 0.0f;
#pragma unroll
                    for (int i = 0; i < 8; i++) s += s_part[i * DD + d];
                    s_q[d] = s / (float)kk;
                }
            } else {
                if (g == 0) s_q[d] = g_hx[c * DD + d];
            }
            __syncthreads();

            int jw = tid >> 5;
            for (int j = jw; j < kk; j += 32) {
                float p = 0.0f;
#pragma unroll
                for (int q = 0; q < 4; q++) {
                    int dd = lane + 32 * q;
                    p += s_inp[j * DD + dd] * s_q[dd];
                }
#pragma unroll
                for (int o = 16; o; o >>= 1) p += __shfl_xor_sync(0xffffffffu, p, o);
                if (lane == 0) s_a[j] = p / sqrtf(128.0f);
            }
            __syncthreads();
            if (tid < 32) {
                float a0 = (tid < kk) ? s_a[tid] : -1e30f;
                float a1 = (tid + 32 < kk) ? s_a[tid + 32] : -1e30f;
                float m = fmaxf(a0, a1);
#pragma unroll
                for (int o = 16; o; o >>= 1) m = fmaxf(m, __shfl_xor_sync(0xffffffffu, m, o));
                float e0 = (tid < kk) ? expf(a0 - m) : 0.0f;
                float e1 = (tid + 32 < kk) ? expf(a1 - m) : 0.0f;
                float s = e0 + e1;
#pragma unroll
                for (int o = 16; o; o >>= 1) s += __shfl_xor_sync(0xffffffffu, s, o);
                if (tid < kk) s_a[tid] = e0 / s;
                if (tid + 32 < kk) s_a[tid + 32] = e1 / s;
            }
            __syncthreads();
            {
                float part = 0.0f;
                for (int j = g; j < kk; j += 8) part += s_a[j] * s_inp[j * DD + d];
                s_part[g * DD + d] = part;
            }
            __syncthreads();
            if (g == 0) {
                float ctx = 0.0f;
#pragma unroll
                for (int i = 0; i < 8; i++) ctx += s_part[i * DD + d];
                s_pre[d] = ctx + ((t > 0) ? s_q[d] : 0.0f);
            }
            __syncthreads();
            {
                float part = 0.0f;
                const int i0 = g * 16;
#pragma unroll 4
                for (int i = i0; i < i0 + 16; i++) part += s_pre[i] * W[i * DD + d];
                s_part[g * DD + d] = part;
            }
            __syncthreads();
            float h = 0.0f;
            if (g == 0) {
                float acc = 0.0f;
#pragma unroll
                for (int i = 0; i < 8; i++) acc += s_part[i * DD + d];
                h = tanhf(acc);
                g_hx[c * DD + d] = h;
                outHxes[(t * CC + c) * DD + d] = h;
                float ss = h * h;
#pragma unroll
                for (int o = 16; o; o >>= 1) ss += __shfl_xor_sync(0xffffffffu, ss, o);
                if (lane == 0) s_red[tid >> 5] = ss;
            }
            __syncthreads();
            if (g == 0) {
                float ns = s_red[0] + s_red[1] + s_red[2] + s_red[3];
                g_hxn[c * DD + d] = h / (sqrtf(ns) + 1e-8f);
            }
        }

        bargen += NB; gridsync(bargen);

        // ======== PHASE B1: per-class compaction, rank-based (no per-entry atomics) ==
        {
            int (*s_wcnt)[17] = reinterpret_cast<int(*)[17]>(s_raw);            // 32x17
            int (*s_woff)[17] = reinterpret_cast<int(*)[17]>(s_raw + 2304);     // 32x17
            int* s_base = reinterpret_cast<int*>(s_raw + 4608);                 // 16

            const int w = tid >> 5;
            int v = bid * 1024 + tid;
            unsigned m = 0u;
            if (v < NN) {
                m = __ldcg(&g_nbr[v]);
                m = (m & KNOWN) ? 0u : (m & 0xFFFFu);
            }
            // stage 1: per-warp per-class counts (no unroll -> low reg pressure)
#pragma unroll 1
            for (int c2 = 0; c2 < CC; c2++) {
                unsigned b = __ballot_sync(0xffffffffu, (m >> c2) & 1u);
                if (lane == 0) s_wcnt[w][c2] = __popc(b);
            }
            __syncthreads();
            // stage 2: per-class scan over 32 warps (warp c2 handles class c2)
            if (tid < CC * 32) {
                int c2 = tid >> 5;
                int lw = lane;
                int val = s_wcnt[lw][c2];
                int x = val;
#pragma unroll
                for (int o = 1; o < 32; o <<= 1) {
                    int y = __shfl_up_sync(0xffffffffu, x, o);
                    if (lw >= o) x += y;
                }
                s_woff[lw][c2] = x - val;
                if (lw == 31) {
                    int total = x;
                    s_base[c2] = total ? atomicAdd(&g_candCnt[c2], total) : 0;
                }
            }
            __syncthreads();
            // stage 3: rank within warp, write
#pragma unroll 1
            for (int c2 = 0; c2 < CC; c2++) {
                unsigned b = __ballot_sync(0xffffffffu, (m >> c2) & 1u);
                if ((m >> c2) & 1u) {
                    int rank = __popc(b & ((1u << lane) - 1u));
                    int pos = s_base[c2] + s_woff[w][c2] + rank;
                    g_clist[(size_t)c2 * NN + pos] = (unsigned)v;
                }
            }
        }

        bargen += NB; gridsync(bargen);

        // ======== PHASE B2: score; flat index over concatenated class segments =======
        {
            float* sh = reinterpret_cast<float*>(s_raw);            // 8192 B
            int* s_pre16 = reinterpret_cast<int*>(s_raw + 8192);    // 17 ints
            for (int i = tid; i < CC * DD; i += 1024) sh[i] = __ldcg(&g_hxn[i]);
            if (tid == 0) {
                int run = 0;
                for (int c2 = 0; c2 < CC; c2++) {
                    s_pre16[c2] = run;
                    run += atomicAdd(&g_candCnt[c2], 0);
                }
                s_pre16[CC] = run;
            }
            __syncthreads();
            const float4* sh4 = reinterpret_cast<const float4*>(sh);
            const float4* es4 = reinterpret_cast<const float4*>(es);
            const int total = s_pre16[CC];
            const int gw = (bid * 1024 + tid) >> 5;
            const int nwarp = NB * 32;
            for (int base = gw * 4; base < total; base += nwarp * 4) {
                int n = total - base; if (n > 4) n = 4;
                float ssum[4], dsum[4];
                unsigned vv[4];
                int ck[4], ok[4];
#pragma unroll
                for (int k = 0; k < 4; k++) {
                    ssum[k] = 0.0f; dsum[k] = 0.0f; vv[k] = 0u; ck[k] = 0; ok[k] = 0;
                    if (k < n) {
                        int idx = base + k;
                        int c2 = 0;
#pragma unroll 1
                        while (c2 < CC - 1 && idx >= s_pre16[c2 + 1]) c2++;
                        int off = idx - s_pre16[c2];
                        ck[k] = c2; ok[k] = off;
                        unsigned v = __ldcg(&g_clist[(size_t)c2 * NN + off]);
                        vv[k] = v;
                        const float4 r = es4[(size_t)v * 32 + lane];
                        const float4 h = sh4[c2 * 32 + lane];
                        ssum[k] = r.x * r.x + r.y * r.y + r.z * r.z + r.w * r.w;
                        dsum[k] = r.x * h.x + r.y * h.y + r.z * h.z + r.w * h.w;
                    }
                }
#pragma unroll
                for (int k = 0; k < 4; k++) {
#pragma unroll
                    for (int o = 16; o; o >>= 1) {
                        ssum[k] += __shfl_xor_sync(0xffffffffu, ssum[k], o);
                        dsum[k] += __shfl_xor_sync(0xffffffffu, dsum[k], o);
                    }
                }
                float sc0 = dsum[0] * (1.0f / (sqrtf(ssum[0]) + 1e-8f));
                float sc1 = dsum[1] * (1.0f / (sqrtf(ssum[1]) + 1e-8f));
                float sc2 = dsum[2] * (1.0f / (sqrtf(ssum[2]) + 1e-8f));
                float sc3 = dsum[3] * (1.0f / (sqrtf(ssum[3]) + 1e-8f));
                if (lane < n) {
                    float score = (lane == 0) ? sc0 : (lane == 1) ? sc1 : (lane == 2) ? sc2 : sc3;
                    unsigned v = (lane == 0) ? vv[0] : (lane == 1) ? vv[1] : (lane == 2) ? vv[2] : vv[3];
                    int c2   = (lane == 0) ? ck[0] : (lane == 1) ? ck[1] : (lane == 2) ? ck[2] : ck[3];
                    int off  = (lane == 0) ? ok[0] : (lane == 1) ? ok[1] : (lane == 2) ? ok[2] : ok[3];
                    unsigned long long key =
                        ((unsigned long long)ford(score) << 32) |
                        (unsigned long long)(0xFFFFFFFFu - v);
                    g_candKeys[(size_t)c2 * NN + off] = key;   // no atomics
                }
            }
        }

        bargen += NB; gridsync(bargen);

        // ================= PHASE C: topk (blocks 0..15), per-class segments ==========
        if (bid < CC) {
            unsigned* hist = reinterpret_cast<unsigned*>(s_raw);
            unsigned long long* sbuf = reinterpret_cast<unsigned long long*>(s_raw + 16384);
            unsigned* s_wsum = reinterpret_cast<unsigned*>(s_raw + 20480);
            int* s_sc = reinterpret_cast<int*>(s_raw + 20608);

            const int c = bid;
            const int wid = tid >> 5;
            const unsigned long long* keys = g_candKeys + (size_t)c * NN;
            int cnt = atomicAdd(&g_candCnt[c], 0);
            __syncthreads();
            if (tid == 0) atomicExch(&g_candCnt[c], 0);   // reset for next iter's B1
            int r = cnt < KK ? cnt : KK;

            unsigned long long prefix = 0ULL;
            int sf = 64;
            if (cnt > 512) {
                int rr = r;
                for (int shift = 52; shift >= 4; shift -= 12) {
                    for (int j = tid; j < 4096; j += 1024) hist[j] = 0u;
                    __syncthreads();
                    for (int i = tid; i < cnt; i += 1024) {
                        unsigned long long key = __ldcg(&keys[i]);
                        if (sf >= 64 || (key >> sf) == prefix)
                            atomicAdd(&hist[(unsigned)((key >> shift) & 0xFFFULL)], 1u);
                    }
                    __syncthreads();
                    int b4 = tid * 4;
                    unsigned lsum = hist[b4] + hist[b4 + 1] + hist[b4 + 2] + hist[b4 + 3];
                    unsigned x = lsum;
#pragma unroll
                    for (int off = 1; off < 32; off <<= 1) {
                        unsigned y = __shfl_down_sync(0xffffffffu, x, off);
                        if (lane + off < 32) x += y;
                    }
                    if (lane == 0) s_wsum[wid] = x;
                    __syncthreads();
                    if (wid == 0) {
                        unsigned w2 = s_wsum[lane];
                        unsigned own = w2;
#pragma unroll
                        for (int off = 1; off < 32; off <<= 1) {
                            unsigned y = __shfl_down_sync(0xffffffffu, w2, off);
                            if (lane + off < 32) w2 += y;
                        }
                        s_wsum[lane] = w2 - own;
                    }
                    __syncthreads();
                    unsigned incl = x + s_wsum[wid];
                    unsigned above = incl - lsum;
                    if (above < (unsigned)rr && incl >= (unsigned)rr) {
                        unsigned cum = above;
                        for (int b = b4 + 3; b >= b4; --b) {
                            unsigned h2 = hist[b];
                            if (cum + h2 >= (unsigned)rr) {
                                s_sc[0] = b;
                                s_sc[1] = (int)cum;
                                int aboveTot = (r - rr) + (int)cum;
                                s_sc[2] = (aboveTot + (int)h2 <= 256) ? 1 : 0;
                                break;
                            }
                            cum += h2;
                        }
                    }
                    __syncthreads();
                    prefix = (prefix << 12) | (unsigned long long)s_sc[0];
                    rr -= s_sc[1];
                    sf = shift;
                    int stop = s_sc[2];
                    __syncthreads();
                    if (stop) break;
                }
            }
            if (tid == 0) s_sc[3] = 0;
            __syncthreads();
            for (int i = tid; i < cnt; i += 1024) {
                unsigned long long key = __ldcg(&keys[i]);
                bool take = (sf >= 64) || ((key >> sf) >= prefix);
                if (take) {
                    int p = atomicAdd(&s_sc[3], 1);
                    if (p < 512) sbuf[p] = key;
                }
            }
            __syncthreads();
            int sc = s_sc[3] < 512 ? s_sc[3] : 512;
            int n = (sc <= 256) ? 256 : 512;
            if (tid < n && tid >= sc) sbuf[tid] = 0ULL;
            __syncthreads();
            for (int kk2 = 2; kk2 <= n; kk2 <<= 1) {
                for (int j = kk2 >> 1; j > 0; j >>= 1) {
                    if (tid < n) {
                        int ixj = tid ^ j;
                        if (ixj > tid) {
                            unsigned long long a = sbuf[tid], b = sbuf[ixj];
                            bool desc = ((tid & kk2) == 0);
                            if (desc ? (a < b) : (a > b)) { sbuf[tid] = b; sbuf[ixj] = a; }
                        }
                    }
                    __syncthreads();
                }
            }
            const int base = (t * CC + c) * KK;
            if (tid < KK && tid < r) {
                unsigned long long key = sbuf[tid];
                int v = (int)(0xFFFFFFFFu - (unsigned)(key & 0xFFFFFFFFull));
                outP[base + tid] = iford((unsigned)(key >> 32));
                outE[base + tid] = (float)v;
                g_last[c * KK + tid] = v;
            }
            if (tid == 0 && r < KK) {
                int fill = r;
                for (int v = 0; v < NN && fill < KK; v++) {
                    unsigned m = __ldcg(&g_nbr[v]);
                    bool valid = (((m >> c) & 1u) != 0u) && !(m & KNOWN);
                    if (!valid) {
                        outP[base + fill] = -1e9f;
                        outE[base + fill] = (float)v;
                        g_last[c * KK + fill] = v;
                        fill++;
                    }
                }
            }
        }

        if (t < NIT - 1) { bargen += NB; gridsync(bargen); }
    }
}

// ---------------- launch ----------------
extern "C" void kernel_launch(void* const* d_in, const int* in_sizes, int n_in,
                              void* d_out, int out_size) {
    const float* es    = (const float*)d_in[0];
    const int*   edges = (const int*)d_in[1];
    const int*   seeds = (const int*)d_in[2];
    const float* W     = (const float*)d_in[3];
    (void)n_in; (void)out_size;

    int e = in_sizes[1] / 2;
    const int* src = edges;
    const int* dst = edges + e;

    float* out  = (float*)d_out;
    float* outP = out;
    float* outE = out + NIT * CC * KK;
    float* outH = out + 2 * NIT * CC * KK;

    k_init<<<128, 256>>>();
    k_main<<<NB, 1024>>>(es, W, seeds, src, dst, e, outP, outE, outH);
}

// round 15
// speedup vs baseline: 1.3742x; 1.1179x over previous
#include <cuda_runtime.h>
#include <math.h>
#include <stdint.h>

#define NN 100000
#define DD 128
#define CC 16
#define SS 16
#define KK 64
#define NIT 4
#define BMW 3125          // bitmap words for 100000 bits
#define HSZ 4096          // hash slots
#define NB  148           // persistent blocks (1 per SM -> all resident, barrier-safe)
#define KNOWN 0x80000000u
#define CHUNK 96          // per-warp staging entries in merged B phase

// ---------------- persistent device state (reset every launch) ----------------
__device__ unsigned int        g_nbr[NN];      // bits 0..15 class mask, bit31 = known
__device__ float               g_hx[CC * DD];
__device__ float               g_hxn[CC * DD];
__device__ int                 g_last[CC * KK];
__device__ int                 g_candCnt[CC];
__device__ unsigned int        g_barCount;
__device__ unsigned long long  g_candKeys[(size_t)CC * NN];    // per-class key lists

// ---------------- helpers ----------------
__device__ __forceinline__ unsigned ford(float f) {
    unsigned u = __float_as_uint(f);
    return (u >> 31) ? ~u : (u | 0x80000000u);
}
__device__ __forceinline__ float iford(unsigned u) {
    unsigned v = (u >> 31) ? (u & 0x7FFFFFFFu) : ~u;
    return __uint_as_float(v);
}
__device__ __forceinline__ int hslot(unsigned v) {
    return (int)((v * 2654435761u) >> 20);
}
__device__ __forceinline__ void gridsync(unsigned target) {
    __syncthreads();
    if (threadIdx.x == 0) {
        __threadfence();
        atomicAdd(&g_barCount, 1u);
        while (*((volatile unsigned*)&g_barCount) < target) __nanosleep(32);
        __threadfence();
    }
    __syncthreads();
}

// ---------------- init (separate tiny launch) ----------------
__global__ void k_init() {
    int stride = gridDim.x * blockDim.x;
    int gt = blockIdx.x * blockDim.x + threadIdx.x;
    for (int v = gt; v < NN; v += stride) g_nbr[v] = 0u;
    if (gt < CC) g_candCnt[gt] = 0;
    if (gt == 0) g_barCount = 0u;
}

// ---------------- the persistent kernel ----------------
__global__ void __launch_bounds__(1024) k_main(
        const float* __restrict__ es, const float* __restrict__ W,
        const int* __restrict__ seeds,
        const int* __restrict__ src, const int* __restrict__ dst, int e,
        float* __restrict__ outP, float* __restrict__ outE,
        float* __restrict__ outHxes) {
    __shared__ __align__(16) unsigned char s_raw[45312];
    const int tid = threadIdx.x;
    const int bid = blockIdx.x;
    const int lane = tid & 31;
    unsigned bargen = 0;

    for (int t = 0; t < NIT; t++) {
        const int per = (t == 0) ? SS : KK;
        const int nm = CC * per;

        // ================= PHASE A: memory (blocks 0..15) | edges (16..147) =========
        if (bid >= CC) {
            unsigned* bm    = reinterpret_cast<unsigned*>(s_raw);
            unsigned* hkey  = reinterpret_cast<unsigned*>(s_raw + 12512);
            unsigned* hmask = reinterpret_cast<unsigned*>(s_raw + 12512 + 16384);
            const int b2 = bid - CC;

            for (int i = tid; i < BMW; i += 1024) bm[i] = 0u;
            for (int i = tid; i < HSZ; i += 1024) { hkey[i] = 0u; hmask[i] = 0u; }
            __syncthreads();
            if (tid < nm) {
                int m = tid;
                unsigned u = (unsigned)((t == 0) ? seeds[m] : __ldcg(&g_last[m]));
                unsigned bit = 1u << (m / per);
                atomicOr(&bm[u >> 5], 1u << (u & 31));
                int s = hslot(u);
                for (;;) {
                    unsigned k = atomicCAS(&hkey[s], 0u, u + 1u);
                    if (k == 0u || k == u + 1u) { atomicOr(&hmask[s], bit); break; }
                    s = (s + 1) & (HSZ - 1);
                }
                if (b2 == 0) atomicOr(&g_nbr[u], KNOWN);
            }
            __syncthreads();

            const int e4 = e >> 2;
            const int4* s4 = reinterpret_cast<const int4*>(src);
            const int stride = (NB - CC) * 1024;
#pragma unroll 4
            for (int i = b2 * 1024 + tid; i < e4; i += stride) {
                int4 s = s4[i];
#pragma unroll
                for (int q = 0; q < 4; q++) {
                    unsigned u = (unsigned)((q == 0) ? s.x : (q == 1) ? s.y : (q == 2) ? s.z : s.w);
                    if ((bm[u >> 5] >> (u & 31)) & 1u) {
                        int sl = hslot(u);
                        unsigned m;
                        for (;;) {
                            unsigned k = hkey[sl];
                            if (k == u + 1u) { m = hmask[sl]; break; }
                            sl = (sl + 1) & (HSZ - 1);
                        }
                        atomicOr(&g_nbr[dst[4 * i + q]], m);
                    }
                }
            }
            int tail = e & 3, tb = e - tail;
            if (b2 == 0 && tid < tail) {
                unsigned u = (unsigned)src[tb + tid];
                if ((bm[u >> 5] >> (u & 31)) & 1u) {
                    int sl = hslot(u);
                    unsigned m;
                    for (;;) {
                        unsigned k = hkey[sl];
                        if (k == u + 1u) { m = hmask[sl]; break; }
                        sl = (sl + 1) & (HSZ - 1);
                    }
                    atomicOr(&g_nbr[dst[tb + tid]], m);
                }
            }
        } else {
            // ---------- memory role ----------
            float* s_inp  = reinterpret_cast<float*>(s_raw);              // 32768
            float* s_part = reinterpret_cast<float*>(s_raw + 32768);      // 4096
            float* s_q    = reinterpret_cast<float*>(s_raw + 36864);      // 512
            float* s_a    = reinterpret_cast<float*>(s_raw + 37376);      // 256
            float* s_pre  = reinterpret_cast<float*>(s_raw + 37632);      // 512
            float* s_red  = reinterpret_cast<float*>(s_raw + 38144);      // 64
            int*   s_nodes= reinterpret_cast<int*>(s_raw + 38208);        // 256

            const int c = bid;
            const int g = tid >> 7;
            const int d = tid & 127;
            const int kk = per;

            if (tid < kk)
                s_nodes[tid] = (t == 0) ? seeds[c * kk + tid] : __ldcg(&g_last[c * KK + tid]);
            __syncthreads();
            // front-batched row gather: up to 8 independent loads per thread
            {
                const int nj = kk >> 3;           // 2 (t==0) or 8
                int nds[8];
                float vals[8];
#pragma unroll
                for (int u = 0; u < 8; u++) if (u < nj) nds[u] = s_nodes[g + 8 * u];
#pragma unroll
                for (int u = 0; u < 8; u++) if (u < nj) vals[u] = es[(size_t)nds[u] * DD + d];
#pragma unroll
                for (int u = 0; u < 8; u++) if (u < nj) s_inp[(g + 8 * u) * DD + d] = vals[u];
            }
            if (t == 0) {
                float part = 0.0f;
                for (int j = g; j < kk; j += 8) part += s_inp[j * DD + d];
                s_part[g * DD + d] = part;
                __syncthreads();
                if (g == 0) {
                    float s = 0.0f;
#pragma unroll
                    for (int i = 0; i < 8; i++) s += s_part[i * DD + d];
                    s_q[d] = s / (float)kk;
                }
            } else {
                if (g == 0) s_q[d] = g_hx[c * DD + d];
            }
            __syncthreads();

            int jw = tid >> 5;
            for (int j = jw; j < kk; j += 32) {
                float p = 0.0f;
#pragma unroll
                for (int q = 0; q < 4; q++) {
                    int dd = lane + 32 * q;
                    p += s_inp[j * DD + dd] * s_q[dd];
                }
#pragma unroll
                for (int o = 16; o; o >>= 1) p += __shfl_xor_sync(0xffffffffu, p, o);
                if (lane == 0) s_a[j] = p / sqrtf(128.0f);
            }
            __syncthreads();
            if (tid < 32) {
                float a0 = (tid < kk) ? s_a[tid] : -1e30f;
                float a1 = (tid + 32 < kk) ? s_a[tid + 32] : -1e30f;
                float m = fmaxf(a0, a1);
#pragma unroll
                for (int o = 16; o; o >>= 1) m = fmaxf(m, __shfl_xor_sync(0xffffffffu, m, o));
                float e0 = (tid < kk) ? expf(a0 - m) : 0.0f;
                float e1 = (tid + 32 < kk) ? expf(a1 - m) : 0.0f;
                float s = e0 + e1;
#pragma unroll
                for (int o = 16; o; o >>= 1) s += __shfl_xor_sync(0xffffffffu, s, o);
                if (tid < kk) s_a[tid] = e0 / s;
                if (tid + 32 < kk) s_a[tid + 32] = e1 / s;
            }
            __syncthreads();
            {
                float part = 0.0f;
                for (int j = g; j < kk; j += 8) part += s_a[j] * s_inp[j * DD + d];
                s_part[g * DD + d] = part;
            }
            __syncthreads();
            if (g == 0) {
                float ctx = 0.0f;
#pragma unroll
                for (int i = 0; i < 8; i++) ctx += s_part[i * DD + d];
                s_pre[d] = ctx + ((t > 0) ? s_q[d] : 0.0f);
            }
            __syncthreads();
            {
                float part = 0.0f;
                const int i0 = g * 16;
#pragma unroll 4
                for (int i = i0; i < i0 + 16; i++) part += s_pre[i] * W[i * DD + d];
                s_part[g * DD + d] = part;
            }
            __syncthreads();
            float h = 0.0f;
            if (g == 0) {
                float acc = 0.0f;
#pragma unroll
                for (int i = 0; i < 8; i++) acc += s_part[i * DD + d];
                h = tanhf(acc);
                g_hx[c * DD + d] = h;
                outHxes[(t * CC + c) * DD + d] = h;
                float ss = h * h;
#pragma unroll
                for (int o = 16; o; o >>= 1) ss += __shfl_xor_sync(0xffffffffu, ss, o);
                if (lane == 0) s_red[tid >> 5] = ss;
            }
            __syncthreads();
            if (g == 0) {
                float ns = s_red[0] + s_red[1] + s_red[2] + s_red[3];
                g_hxn[c * DD + d] = h / (sqrtf(ns) + 1e-8f);
            }
        }

        bargen += NB; gridsync(bargen);

        // ======== PHASE B (merged): compact + score, warp-local staging, no atomics ==
        {
            float* sh = reinterpret_cast<float*>(s_raw);                          // 8192
            int (*s_wcnt)[17] = reinterpret_cast<int(*)[17]>(s_raw + 8192);       // 2176
            int (*s_woff)[17] = reinterpret_cast<int(*)[17]>(s_raw + 10368);      // 2176
            int* s_base = reinterpret_cast<int*>(s_raw + 12544);                  // 64
            unsigned long long* stage =
                reinterpret_cast<unsigned long long*>(s_raw + 12608);             // 32*96*8=24576

            for (int i = tid; i < CC * DD; i += 1024) sh[i] = __ldcg(&g_hxn[i]);

            const int w = tid >> 5;
            int v = bid * 1024 + tid;
            unsigned m = 0u;
            if (v < NN) {
                m = __ldcg(&g_nbr[v]);
                m = (m & KNOWN) ? 0u : (m & 0xFFFFu);
            }
            int pc = __popc(m);
            int x = pc;
#pragma unroll
            for (int o = 1; o < 32; o <<= 1) {
                int y = __shfl_up_sync(0xffffffffu, x, o);
                if (lane >= o) x += y;
            }
            const int excl = x - pc;
            const int wtot = __shfl_sync(0xffffffffu, x, 31);
#pragma unroll 1
            for (int c2 = 0; c2 < CC; c2++) {
                unsigned b = __ballot_sync(0xffffffffu, (m >> c2) & 1u);
                if (lane == 0) s_wcnt[w][c2] = __popc(b);
            }
            __syncthreads();
            if (tid < CC * 32) {
                int c2 = tid >> 5, lw = lane;
                int val = s_wcnt[lw][c2];
                int xx = val;
#pragma unroll
                for (int o = 1; o < 32; o <<= 1) {
                    int y = __shfl_up_sync(0xffffffffu, xx, o);
                    if (lw >= o) xx += y;
                }
                s_woff[lw][c2] = xx - val;
                if (lw == 31) s_base[c2] = xx ? atomicAdd(&g_candCnt[c2], xx) : 0;
            }
            __syncthreads();

            const float4* sh4 = reinterpret_cast<const float4*>(sh);
            const float4* es4 = reinterpret_cast<const float4*>(es);
            unsigned long long* wst = stage + w * CHUNK;

            for (int cb = 0; cb < wtot; cb += CHUNK) {
                int lim = wtot - cb; if (lim > CHUNK) lim = CHUNK;
                // stage warp-global entries [cb, cb+lim): (pos<<32)|(c2<<17)|v
                int li = 0;
#pragma unroll 1
                for (int c2 = 0; c2 < CC; c2++) {
                    unsigned b = __ballot_sync(0xffffffffu, (m >> c2) & 1u);
                    if ((m >> c2) & 1u) {
                        int gi = excl + li;
                        if (gi >= cb && gi < cb + lim) {
                            int rank = __popc(b & ((1u << lane) - 1u));
                            unsigned pos = (unsigned)(s_base[c2] + s_woff[w][c2] + rank);
                            wst[gi - cb] = ((unsigned long long)pos << 32) |
                                           ((unsigned)c2 << 17) | (unsigned)v;
                        }
                        li++;
                    }
                }
                __syncwarp();
                for (int b2 = 0; b2 < lim; b2 += 4) {
                    int n = lim - b2; if (n > 4) n = 4;
                    float ssum[4], dsum[4];
                    unsigned long long e0 = 0, e1 = 0, e2 = 0, e3 = 0;
                    e0 = wst[b2 + 0];
                    if (n > 1) e1 = wst[b2 + 1];
                    if (n > 2) e2 = wst[b2 + 2];
                    if (n > 3) e3 = wst[b2 + 3];
#pragma unroll
                    for (int k = 0; k < 4; k++) {
                        ssum[k] = 0.0f; dsum[k] = 0.0f;
                        if (k < n) {
                            unsigned long long ee = (k == 0) ? e0 : (k == 1) ? e1 : (k == 2) ? e2 : e3;
                            unsigned vv = (unsigned)ee & 0x1FFFFu;
                            unsigned c2 = ((unsigned)ee >> 17) & 0xFu;
                            const float4 r = es4[(size_t)vv * 32 + lane];
                            const float4 h = sh4[c2 * 32 + lane];
                            ssum[k] = r.x * r.x + r.y * r.y + r.z * r.z + r.w * r.w;
                            dsum[k] = r.x * h.x + r.y * h.y + r.z * h.z + r.w * h.w;
                        }
                    }
#pragma unroll
                    for (int k = 0; k < 4; k++) {
#pragma unroll
                        for (int o = 16; o; o >>= 1) {
                            ssum[k] += __shfl_xor_sync(0xffffffffu, ssum[k], o);
                            dsum[k] += __shfl_xor_sync(0xffffffffu, dsum[k], o);
                        }
                    }
                    float sc0 = dsum[0] * (1.0f / (sqrtf(ssum[0]) + 1e-8f));
                    float sc1 = dsum[1] * (1.0f / (sqrtf(ssum[1]) + 1e-8f));
                    float sc2 = dsum[2] * (1.0f / (sqrtf(ssum[2]) + 1e-8f));
                    float sc3 = dsum[3] * (1.0f / (sqrtf(ssum[3]) + 1e-8f));
                    if (lane < n) {
                        float score = (lane == 0) ? sc0 : (lane == 1) ? sc1 : (lane == 2) ? sc2 : sc3;
                        unsigned long long ee = (lane == 0) ? e0 : (lane == 1) ? e1 : (lane == 2) ? e2 : e3;
                        unsigned vv = (unsigned)ee & 0x1FFFFu;
                        unsigned c2 = ((unsigned)ee >> 17) & 0xFu;
                        unsigned pos = (unsigned)(ee >> 32);
                        unsigned long long key =
                            ((unsigned long long)ford(score) << 32) |
                            (unsigned long long)(0xFFFFFFFFu - vv);
                        g_candKeys[(size_t)c2 * NN + pos] = key;
                    }
                }
                __syncwarp();
            }
        }

        bargen += NB; gridsync(bargen);

        // ================= PHASE C: topk (blocks 0..15), per-class segments ==========
        if (bid < CC) {
            unsigned* hist = reinterpret_cast<unsigned*>(s_raw);
            unsigned long long* sbuf = reinterpret_cast<unsigned long long*>(s_raw + 16384);
            unsigned* s_wsum = reinterpret_cast<unsigned*>(s_raw + 20480);
            int* s_sc = reinterpret_cast<int*>(s_raw + 20608);

            const int c = bid;
            const int wid = tid >> 5;
            const unsigned long long* keys = g_candKeys + (size_t)c * NN;
            int cnt = atomicAdd(&g_candCnt[c], 0);
            __syncthreads();
            if (tid == 0) atomicExch(&g_candCnt[c], 0);   // reset for next iter's B
            int r = cnt < KK ? cnt : KK;

            unsigned long long prefix = 0ULL;
            int sf = 64;
            if (cnt > 512) {
                int rr = r;
                for (int shift = 52; shift >= 4; shift -= 12) {
                    for (int j = tid; j < 4096; j += 1024) hist[j] = 0u;
                    __syncthreads();
                    for (int i = tid; i < cnt; i += 1024) {
                        unsigned long long key = __ldcg(&keys[i]);
                        if (sf >= 64 || (key >> sf) == prefix)
                            atomicAdd(&hist[(unsigned)((key >> shift) & 0xFFFULL)], 1u);
                    }
                    __syncthreads();
                    int b4 = tid * 4;
                    unsigned lsum = hist[b4] + hist[b4 + 1] + hist[b4 + 2] + hist[b4 + 3];
                    unsigned x = lsum;
#pragma unroll
                    for (int off = 1; off < 32; off <<= 1) {
                        unsigned y = __shfl_down_sync(0xffffffffu, x, off);
                        if (lane + off < 32) x += y;
                    }
                    if (lane == 0) s_wsum[wid] = x;
                    __syncthreads();
                    if (wid == 0) {
                        unsigned w2 = s_wsum[lane];
                        unsigned own = w2;
#pragma unroll
                        for (int off = 1; off < 32; off <<= 1) {
                            unsigned y = __shfl_down_sync(0xffffffffu, w2, off);
                            if (lane + off < 32) w2 += y;
                        }
                        s_wsum[lane] = w2 - own;
                    }
                    __syncthreads();
                    unsigned incl = x + s_wsum[wid];
                    unsigned above = incl - lsum;
                    if (above < (unsigned)rr && incl >= (unsigned)rr) {
                        unsigned cum = above;
                        for (int b = b4 + 3; b >= b4; --b) {
                            unsigned h2 = hist[b];
                            if (cum + h2 >= (unsigned)rr) {
                                s_sc[0] = b;
                                s_sc[1] = (int)cum;
                                int aboveTot = (r - rr) + (int)cum;
                                s_sc[2] = (aboveTot + (int)h2 <= 256) ? 1 : 0;
                                break;
                            }
                            cum += h2;
                        }
                    }
                    __syncthreads();
                    prefix = (prefix << 12) | (unsigned long long)s_sc[0];
                    rr -= s_sc[1];
                    sf = shift;
                    int stop = s_sc[2];
                    __syncthreads();
                    if (stop) break;
                }
            }
            if (tid == 0) s_sc[3] = 0;
            __syncthreads();
            for (int i = tid; i < cnt; i += 1024) {
                unsigned long long key = __ldcg(&keys[i]);
                bool take = (sf >= 64) || ((key >> sf) >= prefix);
                if (take) {
                    int p = atomicAdd(&s_sc[3], 1);
                    if (p < 512) sbuf[p] = key;
                }
            }
            __syncthreads();
            int sc = s_sc[3] < 512 ? s_sc[3] : 512;
            int n = (sc <= 256) ? 256 : 512;
            if (tid < n && tid >= sc) sbuf[tid] = 0ULL;
            __syncthreads();
            for (int kk2 = 2; kk2 <= n; kk2 <<= 1) {
                for (int j = kk2 >> 1; j > 0; j >>= 1) {
                    if (tid < n) {
                        int ixj = tid ^ j;
                        if (ixj > tid) {
                            unsigned long long a = sbuf[tid], b = sbuf[ixj];
                            bool desc = ((tid & kk2) == 0);
                            if (desc ? (a < b) : (a > b)) { sbuf[tid] = b; sbuf[ixj] = a; }
                        }
                    }
                    __syncthreads();
                }
            }
            const int base = (t * CC + c) * KK;
            if (tid < KK && tid < r) {
                unsigned long long key = sbuf[tid];
                int v = (int)(0xFFFFFFFFu - (unsigned)(key & 0xFFFFFFFFull));
                outP[base + tid] = iford((unsigned)(key >> 32));
                outE[base + tid] = (float)v;
                g_last[c * KK + tid] = v;
            }
            if (tid == 0 && r < KK) {
                int fill = r;
                for (int v = 0; v < NN && fill < KK; v++) {
                    unsigned m = __ldcg(&g_nbr[v]);
                    bool valid = (((m >> c) & 1u) != 0u) && !(m & KNOWN);
                    if (!valid) {
                        outP[base + fill] = -1e9f;
                        outE[base + fill] = (float)v;
                        g_last[c * KK + fill] = v;
                        fill++;
                    }
                }
            }
        }

        if (t < NIT - 1) { bargen += NB; gridsync(bargen); }
    }
}

// ---------------- launch ----------------
extern "C" void kernel_launch(void* const* d_in, const int* in_sizes, int n_in,
                              void* d_out, int out_size) {
    const float* es    = (const float*)d_in[0];
    const int*   edges = (const int*)d_in[1];
    const int*   seeds = (const int*)d_in[2];
    const float* W     = (const float*)d_in[3];
    (void)n_in; (void)out_size;

    int e = in_sizes[1] / 2;
    const int* src = edges;
    const int* dst = edges + e;

    float* out  = (float*)d_out;
    float* outP = out;
    float* outE = out + NIT * CC * KK;
    float* outH = out + 2 * NIT * CC * KK;

    k_init<<<128, 256>>>();
    k_main<<<NB, 1024>>>(es, W, seeds, src, dst, e, outP, outE, outH);
}

// round 16
// speedup vs baseline: 1.6742x; 1.2183x over previous
#include <cuda_runtime.h>
#include <math.h>
#include <stdint.h>

#define NN 100000
#define DD 128
#define CC 16
#define SS 16
#define KK 64
#define NIT 4
#define BMW 3125          // bitmap words for 100000 bits
#define HSZ 4096          // hash slots
#define NB  148           // persistent blocks (1 per SM -> all resident, barrier-safe)
#define NPB 676           // nodes per block in phase B (148*676 >= 100000)
#define KNOWN 0x80000000u
#define CHUNK 96          // per-warp staging entries in merged B phase

// ---------------- persistent device state (reset every launch) ----------------
__device__ unsigned int        g_nbr[NN];      // bits 0..15 class mask, bit31 = known
__device__ float               g_hx[CC * DD];
__device__ float               g_hxn[CC * DD];
__device__ int                 g_last[CC * KK];
__device__ int                 g_candCnt[CC];
__device__ unsigned int        g_barCount;
__device__ unsigned int        g_cdone;        // C-phase completion counter (16 per iter)
__device__ unsigned long long  g_candKeys[(size_t)CC * NN];    // per-class key lists

// ---------------- helpers ----------------
__device__ __forceinline__ unsigned ford(float f) {
    unsigned u = __float_as_uint(f);
    return (u >> 31) ? ~u : (u | 0x80000000u);
}
__device__ __forceinline__ float iford(unsigned u) {
    unsigned v = (u >> 31) ? (u & 0x7FFFFFFFu) : ~u;
    return __uint_as_float(v);
}
__device__ __forceinline__ int hslot(unsigned v) {
    return (int)((v * 2654435761u) >> 20);
}
__device__ __forceinline__ void gridsync(unsigned target) {
    __syncthreads();
    if (threadIdx.x == 0) {
        __threadfence();
        atomicAdd(&g_barCount, 1u);
        while (*((volatile unsigned*)&g_barCount) < target) {}
        __threadfence();
    }
    __syncthreads();
}

// ---------------- init (separate tiny launch) ----------------
__global__ void k_init() {
    int stride = gridDim.x * blockDim.x;
    int gt = blockIdx.x * blockDim.x + threadIdx.x;
    for (int v = gt; v < NN; v += stride) g_nbr[v] = 0u;
    if (gt < CC) g_candCnt[gt] = 0;
    if (gt == 0) { g_barCount = 0u; g_cdone = 0u; }
}

// ---------------- the persistent kernel ----------------
__global__ void __launch_bounds__(1024) k_main(
        const float* __restrict__ es, const float* __restrict__ W,
        const int* __restrict__ seeds,
        const int* __restrict__ src, const int* __restrict__ dst, int e,
        float* __restrict__ outP, float* __restrict__ outE,
        float* __restrict__ outHxes) {
    __shared__ __align__(16) unsigned char s_raw[45312];
    const int tid = threadIdx.x;
    const int bid = blockIdx.x;
    const int lane = tid & 31;
    unsigned bargen = 0;

    for (int t = 0; t < NIT; t++) {
        const int per = (t == 0) ? SS : KK;
        const int nm = CC * per;

        // ================= PHASE A: memory (blocks 0..15) | edges (16..147) =========
        if (bid >= CC) {
            unsigned* bm    = reinterpret_cast<unsigned*>(s_raw);
            unsigned* hkey  = reinterpret_cast<unsigned*>(s_raw + 12512);
            unsigned* hmask = reinterpret_cast<unsigned*>(s_raw + 12512 + 16384);
            const int b2 = bid - CC;

            if (t == 0) {
                for (int i = tid; i < BMW; i += 1024) bm[i] = 0u;
                for (int i = tid; i < HSZ; i += 1024) { hkey[i] = 0u; hmask[i] = 0u; }
                __syncthreads();
            }
            // (t>0: tables zeroed + g_last visibility established during previous C-slot)
            if (tid < nm) {
                int m = tid;
                unsigned u = (unsigned)((t == 0) ? seeds[m] : __ldcg(&g_last[m]));
                unsigned bit = 1u << (m / per);
                atomicOr(&bm[u >> 5], 1u << (u & 31));
                int s = hslot(u);
                for (;;) {
                    unsigned k = atomicCAS(&hkey[s], 0u, u + 1u);
                    if (k == 0u || k == u + 1u) { atomicOr(&hmask[s], bit); break; }
                    s = (s + 1) & (HSZ - 1);
                }
                if (b2 == 0) atomicOr(&g_nbr[u], KNOWN);
            }
            __syncthreads();

            const int e4 = e >> 2;
            const int4* s4 = reinterpret_cast<const int4*>(src);
            const int stride = (NB - CC) * 1024;
#pragma unroll 4
            for (int i = b2 * 1024 + tid; i < e4; i += stride) {
                int4 s = s4[i];
#pragma unroll
                for (int q = 0; q < 4; q++) {
                    unsigned u = (unsigned)((q == 0) ? s.x : (q == 1) ? s.y : (q == 2) ? s.z : s.w);
                    if ((bm[u >> 5] >> (u & 31)) & 1u) {
                        int sl = hslot(u);
                        unsigned m;
                        for (;;) {
                            unsigned k = hkey[sl];
                            if (k == u + 1u) { m = hmask[sl]; break; }
                            sl = (sl + 1) & (HSZ - 1);
                        }
                        atomicOr(&g_nbr[dst[4 * i + q]], m);
                    }
                }
            }
            int tail = e & 3, tb = e - tail;
            if (b2 == 0 && tid < tail) {
                unsigned u = (unsigned)src[tb + tid];
                if ((bm[u >> 5] >> (u & 31)) & 1u) {
                    int sl = hslot(u);
                    unsigned m;
                    for (;;) {
                        unsigned k = hkey[sl];
                        if (k == u + 1u) { m = hmask[sl]; break; }
                        sl = (sl + 1) & (HSZ - 1);
                    }
                    atomicOr(&g_nbr[dst[tb + tid]], m);
                }
            }
        } else {
            // ---------- memory role (block c): node list cached in s_nodes ----------
            float* s_inp  = reinterpret_cast<float*>(s_raw);              // 32768
            float* s_part = reinterpret_cast<float*>(s_raw + 32768);      // 4096
            float* s_q    = reinterpret_cast<float*>(s_raw + 36864);      // 512
            float* s_a    = reinterpret_cast<float*>(s_raw + 37376);      // 256
            float* s_pre  = reinterpret_cast<float*>(s_raw + 37632);      // 512
            float* s_red  = reinterpret_cast<float*>(s_raw + 38144);      // 64
            int*   s_nodes= reinterpret_cast<int*>(s_raw + 38208);        // 256

            const int c = bid;
            const int g = tid >> 7;
            const int d = tid & 127;
            const int kk = per;

            if (t == 0) {
                if (tid < SS) s_nodes[tid] = seeds[c * SS + tid];
                __syncthreads();
            }
            // (t>0: s_nodes filled by this block's own C phase last iteration)

            // front-batched row gather: up to 8 independent loads per thread
            {
                const int nj = kk >> 3;           // 2 (t==0) or 8
                int nds[8];
                float vals[8];
#pragma unroll
                for (int u = 0; u < 8; u++) if (u < nj) nds[u] = s_nodes[g + 8 * u];
#pragma unroll
                for (int u = 0; u < 8; u++) if (u < nj) vals[u] = es[(size_t)nds[u] * DD + d];
#pragma unroll
                for (int u = 0; u < 8; u++) if (u < nj) s_inp[(g + 8 * u) * DD + d] = vals[u];
            }
            if (t == 0) {
                float part = 0.0f;
                for (int j = g; j < kk; j += 8) part += s_inp[j * DD + d];
                s_part[g * DD + d] = part;
                __syncthreads();
                if (g == 0) {
                    float s = 0.0f;
#pragma unroll
                    for (int i = 0; i < 8; i++) s += s_part[i * DD + d];
                    s_q[d] = s / (float)kk;
                }
            } else {
                if (g == 0) s_q[d] = g_hx[c * DD + d];
            }
            __syncthreads();

            int jw = tid >> 5;
            for (int j = jw; j < kk; j += 32) {
                float p = 0.0f;
#pragma unroll
                for (int q = 0; q < 4; q++) {
                    int dd = lane + 32 * q;
                    p += s_inp[j * DD + dd] * s_q[dd];
                }
#pragma unroll
                for (int o = 16; o; o >>= 1) p += __shfl_xor_sync(0xffffffffu, p, o);
                if (lane == 0) s_a[j] = p / sqrtf(128.0f);
            }
            __syncthreads();
            if (tid < 32) {
                float a0 = (tid < kk) ? s_a[tid] : -1e30f;
                float a1 = (tid + 32 < kk) ? s_a[tid + 32] : -1e30f;
                float m = fmaxf(a0, a1);
#pragma unroll
                for (int o = 16; o; o >>= 1) m = fmaxf(m, __shfl_xor_sync(0xffffffffu, m, o));
                float e0 = (tid < kk) ? expf(a0 - m) : 0.0f;
                float e1 = (tid + 32 < kk) ? expf(a1 - m) : 0.0f;
                float s = e0 + e1;
#pragma unroll
                for (int o = 16; o; o >>= 1) s += __shfl_xor_sync(0xffffffffu, s, o);
                if (tid < kk) s_a[tid] = e0 / s;
                if (tid + 32 < kk) s_a[tid + 32] = e1 / s;
            }
            __syncthreads();
            {
                float part = 0.0f;
                for (int j = g; j < kk; j += 8) part += s_a[j] * s_inp[j * DD + d];
                s_part[g * DD + d] = part;
            }
            __syncthreads();
            if (g == 0) {
                float ctx = 0.0f;
#pragma unroll
                for (int i = 0; i < 8; i++) ctx += s_part[i * DD + d];
                s_pre[d] = ctx + ((t > 0) ? s_q[d] : 0.0f);
            }
            __syncthreads();
            {
                float part = 0.0f;
                const int i0 = g * 16;
#pragma unroll 4
                for (int i = i0; i < i0 + 16; i++) part += s_pre[i] * W[i * DD + d];
                s_part[g * DD + d] = part;
            }
            __syncthreads();
            float h = 0.0f;
            if (g == 0) {
                float acc = 0.0f;
#pragma unroll
                for (int i = 0; i < 8; i++) acc += s_part[i * DD + d];
                h = tanhf(acc);
                g_hx[c * DD + d] = h;
                outHxes[(t * CC + c) * DD + d] = h;
                float ss = h * h;
#pragma unroll
                for (int o = 16; o; o >>= 1) ss += __shfl_xor_sync(0xffffffffu, ss, o);
                if (lane == 0) s_red[tid >> 5] = ss;
            }
            __syncthreads();
            if (g == 0) {
                float ns = s_red[0] + s_red[1] + s_red[2] + s_red[3];
                g_hxn[c * DD + d] = h / (sqrtf(ns) + 1e-8f);
            }
        }

        bargen += NB; gridsync(bargen);

        // ======== PHASE B (merged): compact + score, all 148 blocks, no atomics ======
        {
            float* sh = reinterpret_cast<float*>(s_raw);                          // 8192
            int (*s_wcnt)[17] = reinterpret_cast<int(*)[17]>(s_raw + 8192);       // 2176
            int (*s_woff)[17] = reinterpret_cast<int(*)[17]>(s_raw + 10368);      // 2176
            int* s_base = reinterpret_cast<int*>(s_raw + 12544);                  // 64
            unsigned long long* stage =
                reinterpret_cast<unsigned long long*>(s_raw + 12608);             // 24576

            for (int i = tid; i < CC * DD; i += 1024) sh[i] = __ldcg(&g_hxn[i]);

            const int w = tid >> 5;
            int v = bid * NPB + tid;
            unsigned m = 0u;
            if (tid < NPB && v < NN) {
                m = __ldcg(&g_nbr[v]);
                m = (m & KNOWN) ? 0u : (m & 0xFFFFu);
            }
            int pc = __popc(m);
            int x = pc;
#pragma unroll
            for (int o = 1; o < 32; o <<= 1) {
                int y = __shfl_up_sync(0xffffffffu, x, o);
                if (lane >= o) x += y;
            }
            const int excl = x - pc;
            const int wtot = __shfl_sync(0xffffffffu, x, 31);
#pragma unroll 1
            for (int c2 = 0; c2 < CC; c2++) {
                unsigned b = __ballot_sync(0xffffffffu, (m >> c2) & 1u);
                if (lane == 0) s_wcnt[w][c2] = __popc(b);
            }
            __syncthreads();
            if (tid < CC * 32) {
                int c2 = tid >> 5, lw = lane;
                int val = s_wcnt[lw][c2];
                int xx = val;
#pragma unroll
                for (int o = 1; o < 32; o <<= 1) {
                    int y = __shfl_up_sync(0xffffffffu, xx, o);
                    if (lw >= o) xx += y;
                }
                s_woff[lw][c2] = xx - val;
                if (lw == 31) s_base[c2] = xx ? atomicAdd(&g_candCnt[c2], xx) : 0;
            }
            __syncthreads();

            const float4* sh4 = reinterpret_cast<const float4*>(sh);
            const float4* es4 = reinterpret_cast<const float4*>(es);
            unsigned long long* wst = stage + w * CHUNK;

            for (int cb = 0; cb < wtot; cb += CHUNK) {
                int lim = wtot - cb; if (lim > CHUNK) lim = CHUNK;
                int li = 0;
#pragma unroll 1
                for (int c2 = 0; c2 < CC; c2++) {
                    unsigned b = __ballot_sync(0xffffffffu, (m >> c2) & 1u);
                    if ((m >> c2) & 1u) {
                        int gi = excl + li;
                        if (gi >= cb && gi < cb + lim) {
                            int rank = __popc(b & ((1u << lane) - 1u));
                            unsigned pos = (unsigned)(s_base[c2] + s_woff[w][c2] + rank);
                            wst[gi - cb] = ((unsigned long long)pos << 32) |
                                           ((unsigned)c2 << 17) | (unsigned)v;
                        }
                        li++;
                    }
                }
                __syncwarp();
                for (int b2 = 0; b2 < lim; b2 += 4) {
                    int n = lim - b2; if (n > 4) n = 4;
                    float ssum[4], dsum[4];
                    unsigned long long e0 = 0, e1 = 0, e2 = 0, e3 = 0;
                    e0 = wst[b2 + 0];
                    if (n > 1) e1 = wst[b2 + 1];
                    if (n > 2) e2 = wst[b2 + 2];
                    if (n > 3) e3 = wst[b2 + 3];
#pragma unroll
                    for (int k = 0; k < 4; k++) {
                        ssum[k] = 0.0f; dsum[k] = 0.0f;
                        if (k < n) {
                            unsigned long long ee = (k == 0) ? e0 : (k == 1) ? e1 : (k == 2) ? e2 : e3;
                            unsigned vv = (unsigned)ee & 0x1FFFFu;
                            unsigned c2 = ((unsigned)ee >> 17) & 0xFu;
                            const float4 r = es4[(size_t)vv * 32 + lane];
                            const float4 h = sh4[c2 * 32 + lane];
                            ssum[k] = r.x * r.x + r.y * r.y + r.z * r.z + r.w * r.w;
                            dsum[k] = r.x * h.x + r.y * h.y + r.z * h.z + r.w * h.w;
                        }
                    }
#pragma unroll
                    for (int k = 0; k < 4; k++) {
#pragma unroll
                        for (int o = 16; o; o >>= 1) {
                            ssum[k] += __shfl_xor_sync(0xffffffffu, ssum[k], o);
                            dsum[k] += __shfl_xor_sync(0xffffffffu, dsum[k], o);
                        }
                    }
                    float sc0 = dsum[0] * (1.0f / (sqrtf(ssum[0]) + 1e-8f));
                    float sc1 = dsum[1] * (1.0f / (sqrtf(ssum[1]) + 1e-8f));
                    float sc2 = dsum[2] * (1.0f / (sqrtf(ssum[2]) + 1e-8f));
                    float sc3 = dsum[3] * (1.0f / (sqrtf(ssum[3]) + 1e-8f));
                    if (lane < n) {
                        float score = (lane == 0) ? sc0 : (lane == 1) ? sc1 : (lane == 2) ? sc2 : sc3;
                        unsigned long long ee = (lane == 0) ? e0 : (lane == 1) ? e1 : (lane == 2) ? e2 : e3;
                        unsigned vv = (unsigned)ee & 0x1FFFFu;
                        unsigned c2 = ((unsigned)ee >> 17) & 0xFu;
                        unsigned pos = (unsigned)(ee >> 32);
                        unsigned long long key =
                            ((unsigned long long)ford(score) << 32) |
                            (unsigned long long)(0xFFFFFFFFu - vv);
                        g_candKeys[(size_t)c2 * NN + pos] = key;
                    }
                }
                __syncwarp();
            }
        }

        bargen += NB; gridsync(bargen);

        // ===== PHASE C: topk (blocks 0..15); edge blocks pre-zero + flag-wait =======
        if (bid < CC) {
            unsigned* hist = reinterpret_cast<unsigned*>(s_raw);
            unsigned long long* sbuf = reinterpret_cast<unsigned long long*>(s_raw + 16384);
            unsigned* s_wsum = reinterpret_cast<unsigned*>(s_raw + 20480);
            int* s_sc = reinterpret_cast<int*>(s_raw + 20608);
            int* s_nodes = reinterpret_cast<int*>(s_raw + 38208);

            const int c = bid;
            const int wid = tid >> 5;
            const unsigned long long* keys = g_candKeys + (size_t)c * NN;
            int cnt = atomicAdd(&g_candCnt[c], 0);
            __syncthreads();
            if (tid == 0) atomicExch(&g_candCnt[c], 0);   // reset for next iter's B
            int r = cnt < KK ? cnt : KK;

            unsigned long long prefix = 0ULL;
            int sf = 64;
            if (cnt > 128) {
                int rr = r;
                for (int shift = 52; shift >= 4; shift -= 12) {
                    for (int j = tid; j < 4096; j += 1024) hist[j] = 0u;
                    __syncthreads();
                    for (int i = tid; i < cnt; i += 1024) {
                        unsigned long long key = __ldcg(&keys[i]);
                        if (sf >= 64 || (key >> sf) == prefix)
                            atomicAdd(&hist[(unsigned)((key >> shift) & 0xFFFULL)], 1u);
                    }
                    __syncthreads();
                    int b4 = tid * 4;
                    unsigned lsum = hist[b4] + hist[b4 + 1] + hist[b4 + 2] + hist[b4 + 3];
                    unsigned x = lsum;
#pragma unroll
                    for (int off = 1; off < 32; off <<= 1) {
                        unsigned y = __shfl_down_sync(0xffffffffu, x, off);
                        if (lane + off < 32) x += y;
                    }
                    if (lane == 0) s_wsum[wid] = x;
                    __syncthreads();
                    if (wid == 0) {
                        unsigned w2 = s_wsum[lane];
                        unsigned own = w2;
#pragma unroll
                        for (int off = 1; off < 32; off <<= 1) {
                            unsigned y = __shfl_down_sync(0xffffffffu, w2, off);
                            if (lane + off < 32) w2 += y;
                        }
                        s_wsum[lane] = w2 - own;
                    }
                    __syncthreads();
                    unsigned incl = x + s_wsum[wid];
                    unsigned above = incl - lsum;
                    if (above < (unsigned)rr && incl >= (unsigned)rr) {
                        unsigned cum = above;
                        for (int b = b4 + 3; b >= b4; --b) {
                            unsigned h2 = hist[b];
                            if (cum + h2 >= (unsigned)rr) {
                                s_sc[0] = b;
                                s_sc[1] = (int)cum;
                                int aboveTot = (r - rr) + (int)cum;
                                s_sc[2] = (aboveTot + (int)h2 <= 128) ? 1 : 0;
                                break;
                            }
                            cum += h2;
                        }
                    }
                    __syncthreads();
                    prefix = (prefix << 12) | (unsigned long long)s_sc[0];
                    rr -= s_sc[1];
                    sf = shift;
                    int stop = s_sc[2];
                    __syncthreads();
                    if (stop) break;
                }
            }
            if (tid == 0) s_sc[3] = 0;
            __syncthreads();
            for (int i = tid; i < cnt; i += 1024) {
                unsigned long long key = __ldcg(&keys[i]);
                bool take = (sf >= 64) || ((key >> sf) >= prefix);
                if (take) {
                    int p = atomicAdd(&s_sc[3], 1);
                    if (p < 512) sbuf[p] = key;
                }
            }
            __syncthreads();
            int scl = s_sc[3] < 512 ? s_sc[3] : 512;
            // rank-by-counting (keys distinct): rank = #keys greater; top-r sorted output
            const int base = (t * CC + c) * KK;
            if (tid < scl) {
                unsigned long long mykey = sbuf[tid];
                int rank = 0;
                for (int j = 0; j < scl; j++) rank += (sbuf[j] > mykey) ? 1 : 0;
                if (rank < r) {
                    int v = (int)(0xFFFFFFFFu - (unsigned)(mykey & 0xFFFFFFFFull));
                    outP[base + rank] = iford((unsigned)(mykey >> 32));
                    outE[base + rank] = (float)v;
                    g_last[c * KK + rank] = v;
                    s_nodes[rank] = v;
                }
            }
            if (tid == 0 && r < KK) {
                int fill = r;
                for (int v = 0; v < NN && fill < KK; v++) {
                    unsigned m = __ldcg(&g_nbr[v]);
                    bool valid = (((m >> c) & 1u) != 0u) && !(m & KNOWN);
                    if (!valid) {
                        outP[base + fill] = -1e9f;
                        outE[base + fill] = (float)v;
                        g_last[c * KK + fill] = v;
                        s_nodes[fill] = v;
                        fill++;
                    }
                }
            }
            __syncthreads();
            if (tid == 0) {                 // signal: g_last for iteration t ready
                __threadfence();
                atomicAdd(&g_cdone, 1u);
            }
        } else if (t < NIT - 1) {
            // edge blocks: pre-zero tables for next iteration, then wait for all C
            unsigned* bm    = reinterpret_cast<unsigned*>(s_raw);
            unsigned* hkey  = reinterpret_cast<unsigned*>(s_raw + 12512);
            unsigned* hmask = reinterpret_cast<unsigned*>(s_raw + 12512 + 16384);
            for (int i = tid; i < BMW; i += 1024) bm[i] = 0u;
            for (int i = tid; i < HSZ; i += 1024) { hkey[i] = 0u; hmask[i] = 0u; }
            __syncthreads();
            if (tid == 0) {
                unsigned target = 16u * (unsigned)(t + 1);
                while (*((volatile unsigned*)&g_cdone) < target) {}
                __threadfence();
            }
            __syncthreads();
        }
    }
}

// ---------------- launch ----------------
extern "C" void kernel_launch(void* const* d_in, const int* in_sizes, int n_in,
                              void* d_out, int out_size) {
    const float* es    = (const float*)d_in[0];
    const int*   edges = (const int*)d_in[1];
    const int*   seeds = (const int*)d_in[2];
    const float* W     = (const float*)d_in[3];
    (void)n_in; (void)out_size;

    int e = in_sizes[1] / 2;
    const int* src = edges;
    const int* dst = edges + e;

    float* out  = (float*)d_out;
    float* outP = out;
    float* outE = out + NIT * CC * KK;
    float* outH = out + 2 * NIT * CC * KK;

    k_init<<<128, 256>>>();
    k_main<<<NB, 1024>>>(es, W, seeds, src, dst, e, outP, outE, outH);
}

// round 17
// speedup vs baseline: 1.6769x; 1.0016x over previous
#include <cuda_runtime.h>
#include <math.h>
#include <stdint.h>

#define NN 100000
#define DD 128
#define CC 16
#define SS 16
#define KK 64
#define NIT 4
#define BMW 3125          // bitmap words for 100000 bits
#define HSZ 4096          // hash slots
#define NB  296           // persistent blocks (2 per SM, all resident -> barrier-safe)
#define TPB 512
#define NPB 338           // nodes per block in phase B (296*338 >= 100000)
#define KNOWN 0x80000000u
#define CHUNK 96          // per-warp staging entries in merged B phase

// ---------------- persistent device state (reset every launch) ----------------
__device__ unsigned int        g_nbr[NN];      // bits 0..15 class mask, bit31 = known
__device__ float               g_hx[CC * DD];
__device__ float               g_hxn[CC * DD];
__device__ int                 g_last[CC * KK];
__device__ int                 g_candCnt[CC];
__device__ unsigned int        g_barCount;
__device__ unsigned int        g_cdone;        // C-phase completion counter (16 per iter)
__device__ unsigned long long  g_candKeys[(size_t)CC * NN];    // per-class key lists

// ---------------- helpers ----------------
__device__ __forceinline__ unsigned ford(float f) {
    unsigned u = __float_as_uint(f);
    return (u >> 31) ? ~u : (u | 0x80000000u);
}
__device__ __forceinline__ float iford(unsigned u) {
    unsigned v = (u >> 31) ? (u & 0x7FFFFFFFu) : ~u;
    return __uint_as_float(v);
}
__device__ __forceinline__ int hslot(unsigned v) {
    return (int)((v * 2654435761u) >> 20);
}
__device__ __forceinline__ void gridsync(unsigned target) {
    __syncthreads();
    if (threadIdx.x == 0) {
        __threadfence();
        atomicAdd(&g_barCount, 1u);
        while (*((volatile unsigned*)&g_barCount) < target) {}
        __threadfence();
    }
    __syncthreads();
}

// ---------------- init (separate tiny launch) ----------------
__global__ void k_init() {
    int stride = gridDim.x * blockDim.x;
    int gt = blockIdx.x * blockDim.x + threadIdx.x;
    for (int v = gt; v < NN; v += stride) g_nbr[v] = 0u;
    if (gt < CC) g_candCnt[gt] = 0;
    if (gt == 0) { g_barCount = 0u; g_cdone = 0u; }
}

// ---------------- the persistent kernel ----------------
__global__ void __launch_bounds__(TPB, 2) k_main(
        const float* __restrict__ es, const float* __restrict__ W,
        const int* __restrict__ seeds,
        const int* __restrict__ src, const int* __restrict__ dst, int e,
        float* __restrict__ outP, float* __restrict__ outE,
        float* __restrict__ outHxes) {
    __shared__ __align__(16) unsigned char s_raw[45312];
    const int tid = threadIdx.x;
    const int bid = blockIdx.x;
    const int lane = tid & 31;
    unsigned bargen = 0;

    for (int t = 0; t < NIT; t++) {
        const int per = (t == 0) ? SS : KK;
        const int nm = CC * per;

        // ================= PHASE A: memory (blocks 0..15) | edges (16..295) =========
        if (bid >= CC) {
            unsigned* bm    = reinterpret_cast<unsigned*>(s_raw);
            unsigned* hkey  = reinterpret_cast<unsigned*>(s_raw + 12512);
            unsigned* hmask = reinterpret_cast<unsigned*>(s_raw + 12512 + 16384);
            const int b2 = bid - CC;

            if (t == 0) {
                for (int i = tid; i < BMW; i += TPB) bm[i] = 0u;
                for (int i = tid; i < HSZ; i += TPB) { hkey[i] = 0u; hmask[i] = 0u; }
                __syncthreads();
            }
            // (t>0: tables zeroed + g_last visibility established during previous C-slot)
            for (int m = tid; m < nm; m += TPB) {
                unsigned u = (unsigned)((t == 0) ? seeds[m] : __ldcg(&g_last[m]));
                unsigned bit = 1u << (m / per);
                atomicOr(&bm[u >> 5], 1u << (u & 31));
                int s = hslot(u);
                for (;;) {
                    unsigned k = atomicCAS(&hkey[s], 0u, u + 1u);
                    if (k == 0u || k == u + 1u) { atomicOr(&hmask[s], bit); break; }
                    s = (s + 1) & (HSZ - 1);
                }
                if (b2 == 0) atomicOr(&g_nbr[u], KNOWN);
            }
            __syncthreads();

            const int e4 = e >> 2;
            const int4* s4 = reinterpret_cast<const int4*>(src);
            const int stride = (NB - CC) * TPB;
#pragma unroll 4
            for (int i = b2 * TPB + tid; i < e4; i += stride) {
                int4 s = s4[i];
#pragma unroll
                for (int q = 0; q < 4; q++) {
                    unsigned u = (unsigned)((q == 0) ? s.x : (q == 1) ? s.y : (q == 2) ? s.z : s.w);
                    if ((bm[u >> 5] >> (u & 31)) & 1u) {
                        int sl = hslot(u);
                        unsigned m;
                        for (;;) {
                            unsigned k = hkey[sl];
                            if (k == u + 1u) { m = hmask[sl]; break; }
                            sl = (sl + 1) & (HSZ - 1);
                        }
                        atomicOr(&g_nbr[dst[4 * i + q]], m);
                    }
                }
            }
            int tail = e & 3, tb = e - tail;
            if (b2 == 0 && tid < tail) {
                unsigned u = (unsigned)src[tb + tid];
                if ((bm[u >> 5] >> (u & 31)) & 1u) {
                    int sl = hslot(u);
                    unsigned m;
                    for (;;) {
                        unsigned k = hkey[sl];
                        if (k == u + 1u) { m = hmask[sl]; break; }
                        sl = (sl + 1) & (HSZ - 1);
                    }
                    atomicOr(&g_nbr[dst[tb + tid]], m);
                }
            }
        } else {
            // ---------- memory role (block c): 512 threads, 4 groups of 128 ----------
            float* s_inp  = reinterpret_cast<float*>(s_raw);              // 32768
            float* s_part = reinterpret_cast<float*>(s_raw + 32768);      // 2048
            float* s_q    = reinterpret_cast<float*>(s_raw + 35840);      // 512
            float* s_a    = reinterpret_cast<float*>(s_raw + 36352);      // 256
            float* s_pre  = reinterpret_cast<float*>(s_raw + 36608);      // 512
            float* s_red  = reinterpret_cast<float*>(s_raw + 37632);      // 16
            int*   s_nodes= reinterpret_cast<int*>(s_raw + 38208);        // 256

            const int c = bid;
            const int g = tid >> 7;           // 0..3
            const int d = tid & 127;
            const int kk = per;

            if (t == 0) {
                if (tid < SS) s_nodes[tid] = seeds[c * SS + tid];
                __syncthreads();
            }
            // (t>0: s_nodes filled by this block's own C phase last iteration)

            // front-batched row gather: rows j = g + 4*jj, jj in [0, kk/4), 8-wide waves
            {
                const int nj = kk >> 2;       // 4 (t==0) or 16
                for (int p = 0; p < nj; p += 8) {
                    int nds[8]; float vals[8];
#pragma unroll
                    for (int u = 0; u < 8; u++) if (p + u < nj) nds[u] = s_nodes[g + 4 * (p + u)];
#pragma unroll
                    for (int u = 0; u < 8; u++) if (p + u < nj) vals[u] = es[(size_t)nds[u] * DD + d];
#pragma unroll
                    for (int u = 0; u < 8; u++) if (p + u < nj) s_inp[(g + 4 * (p + u)) * DD + d] = vals[u];
                }
            }
            if (t == 0) {
                float part = 0.0f;
                for (int j = g; j < kk; j += 4) part += s_inp[j * DD + d];
                s_part[g * DD + d] = part;
                __syncthreads();
                if (g == 0) {
                    float s = 0.0f;
#pragma unroll
                    for (int i = 0; i < 4; i++) s += s_part[i * DD + d];
                    s_q[d] = s / (float)kk;
                }
            } else {
                if (g == 0) s_q[d] = g_hx[c * DD + d];
            }
            __syncthreads();

            int jw = tid >> 5;                // 0..15
            for (int j = jw; j < kk; j += 16) {
                float p = 0.0f;
#pragma unroll
                for (int q = 0; q < 4; q++) {
                    int dd = lane + 32 * q;
                    p += s_inp[j * DD + dd] * s_q[dd];
                }
#pragma unroll
                for (int o = 16; o; o >>= 1) p += __shfl_xor_sync(0xffffffffu, p, o);
                if (lane == 0) s_a[j] = p / sqrtf(128.0f);
            }
            __syncthreads();
            if (tid < 32) {
                float a0 = (tid < kk) ? s_a[tid] : -1e30f;
                float a1 = (tid + 32 < kk) ? s_a[tid + 32] : -1e30f;
                float m = fmaxf(a0, a1);
#pragma unroll
                for (int o = 16; o; o >>= 1) m = fmaxf(m, __shfl_xor_sync(0xffffffffu, m, o));
                float e0 = (tid < kk) ? expf(a0 - m) : 0.0f;
                float e1 = (tid + 32 < kk) ? expf(a1 - m) : 0.0f;
                float s = e0 + e1;
#pragma unroll
                for (int o = 16; o; o >>= 1) s += __shfl_xor_sync(0xffffffffu, s, o);
                if (tid < kk) s_a[tid] = e0 / s;
                if (tid + 32 < kk) s_a[tid + 32] = e1 / s;
            }
            __syncthreads();
            {
                float part = 0.0f;
                for (int j = g; j < kk; j += 4) part += s_a[j] * s_inp[j * DD + d];
                s_part[g * DD + d] = part;
            }
            __syncthreads();
            if (g == 0) {
                float ctx = 0.0f;
#pragma unroll
                for (int i = 0; i < 4; i++) ctx += s_part[i * DD + d];
                s_pre[d] = ctx + ((t > 0) ? s_q[d] : 0.0f);
            }
            __syncthreads();
            {
                float part = 0.0f;
                const int i0 = g * 32;
#pragma unroll 4
                for (int i = i0; i < i0 + 32; i++) part += s_pre[i] * W[i * DD + d];
                s_part[g * DD + d] = part;
            }
            __syncthreads();
            float h = 0.0f;
            if (g == 0) {
                float acc = 0.0f;
#pragma unroll
                for (int i = 0; i < 4; i++) acc += s_part[i * DD + d];
                h = tanhf(acc);
                g_hx[c * DD + d] = h;
                outHxes[(t * CC + c) * DD + d] = h;
                float ss = h * h;
#pragma unroll
                for (int o = 16; o; o >>= 1) ss += __shfl_xor_sync(0xffffffffu, ss, o);
                if (lane == 0) s_red[tid >> 5] = ss;
            }
            __syncthreads();
            if (g == 0) {
                float ns = s_red[0] + s_red[1] + s_red[2] + s_red[3];
                g_hxn[c * DD + d] = h / (sqrtf(ns) + 1e-8f);
            }
        }

        bargen += NB; gridsync(bargen);

        // ======== PHASE B (merged): compact + score, all 296 blocks, no atomics ======
        {
            float* sh = reinterpret_cast<float*>(s_raw);                          // 8192
            int (*s_wcnt)[17] = reinterpret_cast<int(*)[17]>(s_raw + 8192);       // 16x17
            int (*s_woff)[17] = reinterpret_cast<int(*)[17]>(s_raw + 9280);       // 16x17
            int* s_base = reinterpret_cast<int*>(s_raw + 10368);                  // 64
            unsigned long long* stage =
                reinterpret_cast<unsigned long long*>(s_raw + 10432);             // 16*96*8=12288

            for (int i = tid; i < CC * DD; i += TPB) sh[i] = __ldcg(&g_hxn[i]);

            const int w = tid >> 5;           // 0..15
            int v = bid * NPB + tid;
            unsigned m = 0u;
            if (tid < NPB && v < NN) {
                m = __ldcg(&g_nbr[v]);
                m = (m & KNOWN) ? 0u : (m & 0xFFFFu);
            }
            int pc = __popc(m);
            int x = pc;
#pragma unroll
            for (int o = 1; o < 32; o <<= 1) {
                int y = __shfl_up_sync(0xffffffffu, x, o);
                if (lane >= o) x += y;
            }
            const int excl = x - pc;
            const int wtot = __shfl_sync(0xffffffffu, x, 31);
#pragma unroll 1
            for (int c2 = 0; c2 < CC; c2++) {
                unsigned b = __ballot_sync(0xffffffffu, (m >> c2) & 1u);
                if (lane == 0) s_wcnt[w][c2] = __popc(b);
            }
            __syncthreads();
            {   // per-class scan over 16 warps: warp c2 (= tid>>5) handles class c2
                int c2 = tid >> 5, lw = lane;
                int val = (lw < 16) ? s_wcnt[lw][c2] : 0;
                int xx = val;
#pragma unroll
                for (int o = 1; o < 32; o <<= 1) {
                    int y = __shfl_up_sync(0xffffffffu, xx, o);
                    if (lw >= o) xx += y;
                }
                if (lw < 16) s_woff[lw][c2] = xx - val;
                if (lw == 31) s_base[c2] = xx ? atomicAdd(&g_candCnt[c2], xx) : 0;
            }
            __syncthreads();

            const float4* sh4 = reinterpret_cast<const float4*>(sh);
            const float4* es4 = reinterpret_cast<const float4*>(es);
            unsigned long long* wst = stage + w * CHUNK;

            for (int cb = 0; cb < wtot; cb += CHUNK) {
                int lim = wtot - cb; if (lim > CHUNK) lim = CHUNK;
                int li = 0;
#pragma unroll 1
                for (int c2 = 0; c2 < CC; c2++) {
                    unsigned b = __ballot_sync(0xffffffffu, (m >> c2) & 1u);
                    if ((m >> c2) & 1u) {
                        int gi = excl + li;
                        if (gi >= cb && gi < cb + lim) {
                            int rank = __popc(b & ((1u << lane) - 1u));
                            unsigned pos = (unsigned)(s_base[c2] + s_woff[w][c2] + rank);
                            wst[gi - cb] = ((unsigned long long)pos << 32) |
                                           ((unsigned)c2 << 17) | (unsigned)v;
                        }
                        li++;
                    }
                }
                __syncwarp();
                for (int b2 = 0; b2 < lim; b2 += 4) {
                    int n = lim - b2; if (n > 4) n = 4;
                    float ssum[4], dsum[4];
                    unsigned long long e0 = 0, e1 = 0, e2 = 0, e3 = 0;
                    e0 = wst[b2 + 0];
                    if (n > 1) e1 = wst[b2 + 1];
                    if (n > 2) e2 = wst[b2 + 2];
                    if (n > 3) e3 = wst[b2 + 3];
#pragma unroll
                    for (int k = 0; k < 4; k++) {
                        ssum[k] = 0.0f; dsum[k] = 0.0f;
                        if (k < n) {
                            unsigned long long ee = (k == 0) ? e0 : (k == 1) ? e1 : (k == 2) ? e2 : e3;
                            unsigned vv = (unsigned)ee & 0x1FFFFu;
                            unsigned c2 = ((unsigned)ee >> 17) & 0xFu;
                            const float4 r = es4[(size_t)vv * 32 + lane];
                            const float4 h = sh4[c2 * 32 + lane];
                            ssum[k] = r.x * r.x + r.y * r.y + r.z * r.z + r.w * r.w;
                            dsum[k] = r.x * h.x + r.y * h.y + r.z * h.z + r.w * h.w;
                        }
                    }
#pragma unroll
                    for (int k = 0; k < 4; k++) {
#pragma unroll
                        for (int o = 16; o; o >>= 1) {
                            ssum[k] += __shfl_xor_sync(0xffffffffu, ssum[k], o);
                            dsum[k] += __shfl_xor_sync(0xffffffffu, dsum[k], o);
                        }
                    }
                    float sc0 = dsum[0] * (1.0f / (sqrtf(ssum[0]) + 1e-8f));
                    float sc1 = dsum[1] * (1.0f / (sqrtf(ssum[1]) + 1e-8f));
                    float sc2 = dsum[2] * (1.0f / (sqrtf(ssum[2]) + 1e-8f));
                    float sc3 = dsum[3] * (1.0f / (sqrtf(ssum[3]) + 1e-8f));
                    if (lane < n) {
                        float score = (lane == 0) ? sc0 : (lane == 1) ? sc1 : (lane == 2) ? sc2 : sc3;
                        unsigned long long ee = (lane == 0) ? e0 : (lane == 1) ? e1 : (lane == 2) ? e2 : e3;
                        unsigned vv = (unsigned)ee & 0x1FFFFu;
                        unsigned c2 = ((unsigned)ee >> 17) & 0xFu;
                        unsigned pos = (unsigned)(ee >> 32);
                        unsigned long long key =
                            ((unsigned long long)ford(score) << 32) |
                            (unsigned long long)(0xFFFFFFFFu - vv);
                        g_candKeys[(size_t)c2 * NN + pos] = key;
                    }
                }
                __syncwarp();
            }
        }

        bargen += NB; gridsync(bargen);

        // ===== PHASE C: topk (blocks 0..15); edge blocks pre-zero + flag-wait =======
        if (bid < CC) {
            unsigned* hist = reinterpret_cast<unsigned*>(s_raw);
            unsigned long long* sbuf = reinterpret_cast<unsigned long long*>(s_raw + 16384);
            unsigned* s_wsum = reinterpret_cast<unsigned*>(s_raw + 20480);
            int* s_sc = reinterpret_cast<int*>(s_raw + 20608);
            int* s_nodes = reinterpret_cast<int*>(s_raw + 38208);

            const int c = bid;
            const int wid = tid >> 5;         // 0..15
            const unsigned long long* keys = g_candKeys + (size_t)c * NN;
            int cnt = atomicAdd(&g_candCnt[c], 0);
            __syncthreads();
            if (tid == 0) atomicExch(&g_candCnt[c], 0);   // reset for next iter's B
            int r = cnt < KK ? cnt : KK;

            unsigned long long prefix = 0ULL;
            int sf = 64;
            if (cnt > 128) {
                int rr = r;
                for (int shift = 52; shift >= 4; shift -= 12) {
                    for (int j = tid; j < 4096; j += TPB) hist[j] = 0u;
                    __syncthreads();
                    for (int i = tid; i < cnt; i += TPB) {
                        unsigned long long key = __ldcg(&keys[i]);
                        if (sf >= 64 || (key >> sf) == prefix)
                            atomicAdd(&hist[(unsigned)((key >> shift) & 0xFFFULL)], 1u);
                    }
                    __syncthreads();
                    int b8 = tid * 8;
                    unsigned lsum = 0;
#pragma unroll
                    for (int j = 0; j < 8; j++) lsum += hist[b8 + j];
                    unsigned x = lsum;
#pragma unroll
                    for (int off = 1; off < 32; off <<= 1) {
                        unsigned y = __shfl_down_sync(0xffffffffu, x, off);
                        if (lane + off < 32) x += y;
                    }
                    if (lane == 0) s_wsum[wid] = x;
                    __syncthreads();
                    if (wid == 0) {
                        unsigned w2 = (lane < 16) ? s_wsum[lane] : 0u;
                        unsigned own = w2;
#pragma unroll
                        for (int off = 1; off < 32; off <<= 1) {
                            unsigned y = __shfl_down_sync(0xffffffffu, w2, off);
                            if (lane + off < 32) w2 += y;
                        }
                        if (lane < 16) s_wsum[lane] = w2 - own;
                    }
                    __syncthreads();
                    unsigned incl = x + s_wsum[wid];
                    unsigned above = incl - lsum;
                    if (above < (unsigned)rr && incl >= (unsigned)rr) {
                        unsigned cum = above;
                        for (int b = b8 + 7; b >= b8; --b) {
                            unsigned h2 = hist[b];
                            if (cum + h2 >= (unsigned)rr) {
                                s_sc[0] = b;
                                s_sc[1] = (int)cum;
                                int aboveTot = (r - rr) + (int)cum;
                                s_sc[2] = (aboveTot + (int)h2 <= 128) ? 1 : 0;
                                break;
                            }
                            cum += h2;
                        }
                    }
                    __syncthreads();
                    prefix = (prefix << 12) | (unsigned long long)s_sc[0];
                    rr -= s_sc[1];
                    sf = shift;
                    int stop = s_sc[2];
                    __syncthreads();
                    if (stop) break;
                }
            }
            if (tid == 0) s_sc[3] = 0;
            __syncthreads();
            for (int i = tid; i < cnt; i += TPB) {
                unsigned long long key = __ldcg(&keys[i]);
                bool take = (sf >= 64) || ((key >> sf) >= prefix);
                if (take) {
                    int p = atomicAdd(&s_sc[3], 1);
                    if (p < 512) sbuf[p] = key;
                }
            }
            __syncthreads();
            int scl = s_sc[3] < 512 ? s_sc[3] : 512;
            // rank-by-counting (keys distinct): rank = #keys greater; top-r sorted output
            const int base = (t * CC + c) * KK;
            if (tid < scl) {
                unsigned long long mykey = sbuf[tid];
                int rank = 0;
                for (int j = 0; j < scl; j++) rank += (sbuf[j] > mykey) ? 1 : 0;
                if (rank < r) {
                    int v = (int)(0xFFFFFFFFu - (unsigned)(mykey & 0xFFFFFFFFull));
                    outP[base + rank] = iford((unsigned)(mykey >> 32));
                    outE[base + rank] = (float)v;
                    g_last[c * KK + rank] = v;
                    s_nodes[rank] = v;
                }
            }
            if (tid == 0 && r < KK) {
                int fill = r;
                for (int v = 0; v < NN && fill < KK; v++) {
                    unsigned m = __ldcg(&g_nbr[v]);
                    bool valid = (((m >> c) & 1u) != 0u) && !(m & KNOWN);
                    if (!valid) {
                        outP[base + fill] = -1e9f;
                        outE[base + fill] = (float)v;
                        g_last[c * KK + fill] = v;
                        s_nodes[fill] = v;
                        fill++;
                    }
                }
            }
            __syncthreads();
            if (tid == 0) {                 // signal: g_last for iteration t ready
                __threadfence();
                atomicAdd(&g_cdone, 1u);
            }
        } else if (t < NIT - 1) {
            // edge blocks: pre-zero tables for next iteration, then wait for all C
            unsigned* bm    = reinterpret_cast<unsigned*>(s_raw);
            unsigned* hkey  = reinterpret_cast<unsigned*>(s_raw + 12512);
            unsigned* hmask = reinterpret_cast<unsigned*>(s_raw + 12512 + 16384);
            for (int i = tid; i < BMW; i += TPB) bm[i] = 0u;
            for (int i = tid; i < HSZ; i += TPB) { hkey[i] = 0u; hmask[i] = 0u; }
            __syncthreads();
            if (tid == 0) {
                unsigned target = 16u * (unsigned)(t + 1);
                while (*((volatile unsigned*)&g_cdone) < target) {}
                __threadfence();
            }
            __syncthreads();
        }
    }
}

// ---------------- launch ----------------
extern "C" void kernel_launch(void* const* d_in, const int* in_sizes, int n_in,
                              void* d_out, int out_size) {
    const float* es    = (const float*)d_in[0];
    const int*   edges = (const int*)d_in[1];
    const int*   seeds = (const int*)d_in[2];
    const float* W     = (const float*)d_in[3];
    (void)n_in; (void)out_size;

    int e = in_sizes[1] / 2;
    const int* src = edges;
    const int* dst = edges + e;

    float* out  = (float*)d_out;
    float* outP = out;
    float* outE = out + NIT * CC * KK;
    float* outH = out + 2 * NIT * CC * KK;

    k_init<<<128, 256>>>();
    k_main<<<NB, TPB>>>(es, W, seeds, src, dst, e, outP, outE, outH);
}